// round 7
// baseline (speedup 1.0000x reference)
#include <cuda_runtime.h>
#include <math.h>

// ---------------------------------------------------------------------------
// Static device scratch (ping-pong A/B + persistent skip buffers).
// ---------------------------------------------------------------------------
__device__ float g_SA[25165824];
__device__ float g_SB[41943040];
__device__ float g_C1[8388608];   // (4,32,256,256)
__device__ float g_C2[8388608];   // (4,128,128,128)
__device__ float g_C3[4194304];   // (4,256,64,64)
__device__ float g_BNscale[512];
__device__ float g_BNshift[512];

static inline int cdiv(int a, int b) { return (a + b - 1) / b; }

__device__ __forceinline__ float mishf(float x) {
    float sp = fmaxf(x, 0.f) + log1pf(expf(-fabsf(x)));
    return x * tanhf(sp);
}

// ---------------------------------------------------------------------------
// Generic direct conv + bias + mish, wide-LDS edition.
// Block: 128 threads -> 32 output channels x (8 rows x 16 cols) tile, 1 batch.
// Requires: Ci % 8 == 0, Co % 32 == 0, Ho % 8 == 0, Wo % 16 == 0.
//  - weights staged in smem transposed [ci][ij][co] so the 4 co-weights a
//    thread needs are one aligned LDS.128
//  - input tile rows padded to XWP=20 floats (80B) so each row's 11-12 taps
//    load as 3x LDS.128
// ---------------------------------------------------------------------------
template<int K>
__global__ __launch_bounds__(128)
void conv_mish_kernel(const float* __restrict__ in, const float* __restrict__ wt,
                      const float* __restrict__ bias, float* __restrict__ out,
                      int Ci, int Hi, int Wi, int Co, int Ho, int Wo, int pad)
{
    constexpr int K2    = K * K;
    constexpr int CI_CH = 8;
    constexpr int CO_T  = 32;
    constexpr int TH    = 8;
    constexpr int TW    = 16;
    constexpr int XH    = TH + K - 1;
    constexpr int XW    = TW + K - 1;          // 18 (K=3) / 19 (K=4)
    constexpr int XWP   = 20;                  // padded row: 80B, 16B-aligned
    constexpr int PER   = CI_CH * K2;          // weight rems per ci-chunk

    __shared__ __align__(16) float ws[PER * CO_T];          // [rem][co]
    __shared__ __align__(16) float xs[CI_CH * XH * XWP];

    const int b   = blockIdx.z;
    const int co0 = blockIdx.y * CO_T;
    const int ntx = Wo / TW;
    const int ty  = blockIdx.x / ntx;
    const int tx  = blockIdx.x - ty * ntx;
    const int y0  = ty * TH;
    const int x0  = tx * TW;

    const int tid = threadIdx.x;
    const int cog = tid >> 4;              // 0..7 -> co_local = cog*4
    const int pg  = tid & 15;
    const int r   = pg >> 1;               // row within tile (0..7)
    const int c0  = (pg & 1) * 8;          // col base within tile (0 or 8)

    const int wco  = tid & 31;             // gather mapping for weight staging
    const int wrem0 = tid >> 5;

    float acc[4][8];
#pragma unroll
    for (int a = 0; a < 4; a++)
#pragma unroll
        for (int p = 0; p < 8; p++) acc[a][p] = 0.f;

    const float* inb = in + (size_t)b * Ci * Hi * Wi;
    const float4* ws4 = (const float4*)ws;

    for (int ci0 = 0; ci0 < Ci; ci0 += CI_CH) {
        // --- weights: global [co][ci][ij] -> smem [rem= ci*K2+ij][co] ---
        // lane's co fixed (tid&31); rem strides by 4 -> per-lane addresses are
        // consecutive in global (L1-friendly); smem stores conflict-free.
        {
            const float* wg = wt + (size_t)(co0 + wco) * Ci * K2 + (size_t)ci0 * K2;
#pragma unroll
            for (int rem = wrem0; rem < PER; rem += 4)
                ws[rem * CO_T + wco] = wg[rem];
        }
        // --- input tile with halo, padded to XWP stride ---
        for (int idx = tid; idx < CI_CH * XH * XWP; idx += 128) {
            int ci  = idx / (XH * XWP);
            int rem = idx - ci * (XH * XWP);
            int yy  = rem / XWP;
            int xx  = rem - yy * XWP;
            int gy  = y0 - pad + yy;
            int gx  = x0 - pad + xx;
            float v = 0.f;
            if (gy >= 0 && gy < Hi && gx >= 0 && gx < Wi && xx < XW)
                v = inb[(size_t)(ci0 + ci) * Hi * Wi + (size_t)gy * Wi + gx];
            xs[idx] = v;
        }
        __syncthreads();

#pragma unroll
        for (int ci = 0; ci < CI_CH; ci++) {
            const float* xb = &xs[ci * XH * XWP];
#pragma unroll
            for (int i = 0; i < K; i++) {
                const float4* xp = (const float4*)(xb + (r + i) * XWP + c0);
                float4 A0 = xp[0], A1 = xp[1], A2 = xp[2];
                float xr[12] = {A0.x, A0.y, A0.z, A0.w,
                                A1.x, A1.y, A1.z, A1.w,
                                A2.x, A2.y, A2.z, A2.w};
#pragma unroll
                for (int j = 0; j < K; j++) {
                    float4 w = ws4[((ci * K2 + i * K + j) * CO_T + cog * 4) >> 2];
#pragma unroll
                    for (int p = 0; p < 8; p++) {
                        float xv = xr[j + p];
                        acc[0][p] = fmaf(w.x, xv, acc[0][p]);
                        acc[1][p] = fmaf(w.y, xv, acc[1][p]);
                        acc[2][p] = fmaf(w.z, xv, acc[2][p]);
                        acc[3][p] = fmaf(w.w, xv, acc[3][p]);
                    }
                }
            }
        }
        __syncthreads();
    }

#pragma unroll
    for (int a = 0; a < 4; a++) {
        int co   = co0 + cog * 4 + a;
        float bv = bias[co];
        float* op = out + ((size_t)b * Co + co) * Ho * Wo
                        + (size_t)(y0 + r) * Wo + x0 + c0;
#pragma unroll
        for (int p = 0; p < 8; p++)
            op[p] = mishf(acc[a][p] + bv);
    }
}

// ---------------------------------------------------------------------------
// Per-sample dynamic conv (Ci=1, K=4, pad=1) + mish. x:(4,1,256,256),
// w:(4,32,4,4) -> out:(4,32,255,255).
// ---------------------------------------------------------------------------
__global__ __launch_bounds__(256)
void dyn_conv_mish(const float* __restrict__ x, const float* __restrict__ w,
                   float* __restrict__ out)
{
    const int H = 256, HO = 255;
    __shared__ float ws[32 * 16];
    __shared__ float xs[19][19];

    int b  = blockIdx.z;
    int y0 = blockIdx.y * 16;
    int x0 = blockIdx.x * 16;
    int tid = threadIdx.x;

    for (int i = tid; i < 512; i += 256) ws[i] = w[b * 512 + i];
    for (int i = tid; i < 19 * 19; i += 256) {
        int yy = i / 19, xx = i - yy * 19;
        int gy = y0 - 1 + yy, gx = x0 - 1 + xx;
        xs[yy][xx] = (gy >= 0 && gy < H && gx >= 0 && gx < H)
                     ? x[(size_t)b * H * H + (size_t)gy * H + gx] : 0.f;
    }
    __syncthreads();

    int r  = tid >> 4;
    int cl = tid & 15;
    int oy = y0 + r, ox = x0 + cl;
    if (oy >= HO || ox >= HO) return;

    float xr[16];
#pragma unroll
    for (int i = 0; i < 4; i++)
#pragma unroll
        for (int j = 0; j < 4; j++) xr[i * 4 + j] = xs[r + i][cl + j];

    float* op = out + (size_t)b * 32 * HO * HO + (size_t)oy * HO + ox;
#pragma unroll
    for (int co = 0; co < 32; co++) {
        float a = 0.f;
#pragma unroll
        for (int t = 0; t < 16; t++) a = fmaf(xr[t], ws[co * 16 + t], a);
        op[(size_t)co * HO * HO] = mishf(a);
    }
}

// ---------------------------------------------------------------------------
__global__ void maxpool_kernel(const float* __restrict__ in, float* __restrict__ out,
                               int BC, int Hi, int Wi)
{
    int Ho = Hi >> 1, Wo = Wi >> 1;
    int total = BC * Ho * Wo;
    int n = blockIdx.x * blockDim.x + threadIdx.x;
    if (n >= total) return;
    int xw = n % Wo; int t = n / Wo;
    int y  = t % Ho; int bc = t / Ho;
    const float* p = in + ((size_t)bc * Hi + 2 * y) * Wi + 2 * xw;
    out[n] = fmaxf(fmaxf(p[0], p[1]), fmaxf(p[Wi], p[Wi + 1]));
}

// ---------------------------------------------------------------------------
// Bilinear x2 upsample, align_corners=True, optional per-channel affine (BN),
// writes into channel-offset region of a concat buffer.
// ---------------------------------------------------------------------------
__global__ void up2_kernel(const float* __restrict__ in, float* __restrict__ out,
                           int C, int H, int W, int dstC, int coff,
                           const float* __restrict__ scale,
                           const float* __restrict__ shift)
{
    int Ho = 2 * H, Wo = 2 * W;
    long long total = (long long)4 * C * Ho * Wo;
    long long n = (long long)blockIdx.x * blockDim.x + threadIdx.x;
    if (n >= total) return;
    int ox = (int)(n % Wo); long long t = n / Wo;
    int oy = (int)(t % Ho); t /= Ho;
    int c  = (int)(t % C);  int b = (int)(t / C);

    float ry = (float)((double)(H - 1) / (double)(2 * H - 1));
    float rx = (float)((double)(W - 1) / (double)(2 * W - 1));
    float sy = (float)oy * ry;
    float sx = (float)ox * rx;
    int y0i = (int)sy;
    int x0i = (int)sx;
    float fy = sy - (float)y0i;
    float fx = sx - (float)x0i;
    int y1i = min(y0i + 1, H - 1);
    int x1i = min(x0i + 1, W - 1);

    const float* p = in + ((size_t)b * C + c) * H * W;
    float a0 = p[(size_t)y0i * W + x0i] * (1.f - fy) + p[(size_t)y1i * W + x0i] * fy;
    float a1 = p[(size_t)y0i * W + x1i] * (1.f - fy) + p[(size_t)y1i * W + x1i] * fy;
    float v  = a0 * (1.f - fx) + a1 * fx;
    if (scale) v = v * scale[c] + shift[c];
    out[((size_t)(b * dstC + coff + c) * Ho + oy) * Wo + ox] = v;
}

// ---------------------------------------------------------------------------
__global__ void concat_copy(const float4* __restrict__ src, float* __restrict__ dst,
                            int C, int HW, int dstC, int coff)
{
    int HW4 = HW >> 2;
    int total = 4 * C * HW4;
    int n = blockIdx.x * blockDim.x + threadIdx.x;
    if (n >= total) return;
    int i = n % HW4; int t = n / HW4;
    int c = t % C;   int b = t / C;
    ((float4*)(dst + (size_t)(b * dstC + coff + c) * HW))[i] = src[n];
}

// ---------------------------------------------------------------------------
// BatchNorm batch-stats -> per-channel affine (scale, shift), two-pass.
// ---------------------------------------------------------------------------
__global__ __launch_bounds__(256)
void bn_stats_kernel(const float* __restrict__ h, const float* __restrict__ g,
                     const float* __restrict__ be, float* __restrict__ scale,
                     float* __restrict__ shift)
{
    __shared__ float red[256];
    int c   = blockIdx.x;
    int tid = threadIdx.x;

    float s = 0.f;
    for (int b = 0; b < 4; b++) {
        const float* p = h + ((size_t)b * 512 + c) * 1024;
        for (int i = tid; i < 1024; i += 256) s += p[i];
    }
    red[tid] = s; __syncthreads();
    for (int o = 128; o > 0; o >>= 1) {
        if (tid < o) red[tid] += red[tid + o];
        __syncthreads();
    }
    float mean = red[0] * (1.f / 4096.f);
    __syncthreads();

    float q = 0.f;
    for (int b = 0; b < 4; b++) {
        const float* p = h + ((size_t)b * 512 + c) * 1024;
        for (int i = tid; i < 1024; i += 256) { float d = p[i] - mean; q += d * d; }
    }
    red[tid] = q; __syncthreads();
    for (int o = 128; o > 0; o >>= 1) {
        if (tid < o) red[tid] += red[tid + o];
        __syncthreads();
    }
    if (tid == 0) {
        float var = red[0] * (1.f / 4096.f);
        float sc  = g[c] * rsqrtf(var + 1e-5f);
        scale[c] = sc;
        shift[c] = be[c] - mean * sc;
    }
}

// ---------------------------------------------------------------------------
// Final 1x1 conv, Co=1, no activation.
// ---------------------------------------------------------------------------
__global__ void conv1x1_out(const float* __restrict__ in, const float* __restrict__ wl,
                            const float* __restrict__ bl, float* __restrict__ out)
{
    __shared__ float w[32];
    if (threadIdx.x < 32) w[threadIdx.x] = wl[threadIdx.x];
    __syncthreads();
    int n = blockIdx.x * blockDim.x + threadIdx.x;
    if (n >= 4 * 65536) return;
    int b = n >> 16;
    int i = n & 65535;
    const float* p = in + (size_t)b * 32 * 65536 + i;
    float s = bl[0];
#pragma unroll
    for (int c = 0; c < 32; c++) s = fmaf(p[(size_t)c * 65536], w[c], s);
    out[n] = s;
}

// ---------------------------------------------------------------------------
// Host side
// ---------------------------------------------------------------------------
static void conv3(const float* in, const float* wt, const float* bs, float* out,
                  int Ci, int HW, int Co)
{
    dim3 g((HW / 8) * (HW / 16), Co / 32, 4);
    conv_mish_kernel<3><<<g, 128>>>(in, wt, bs, out, Ci, HW, HW, Co, HW, HW, 1);
}

extern "C" void kernel_launch(void* const* d_in, const int* in_sizes, int n_in,
                              void* d_out, int out_size)
{
    const float* X    = (const float*)d_in[0];
    const float* W    = (const float*)d_in[1];
    const float* d1w  = (const float*)d_in[2];
    const float* d1b  = (const float*)d_in[3];
    const float* w2a  = (const float*)d_in[4];
    const float* b2a  = (const float*)d_in[5];
    const float* w2b  = (const float*)d_in[6];
    const float* b2b  = (const float*)d_in[7];
    const float* w3a  = (const float*)d_in[8];
    const float* b3a  = (const float*)d_in[9];
    const float* w3b  = (const float*)d_in[10];
    const float* b3b  = (const float*)d_in[11];
    const float* w4a  = (const float*)d_in[12];
    const float* b4a  = (const float*)d_in[13];
    const float* w4b  = (const float*)d_in[14];
    const float* b4b  = (const float*)d_in[15];
    const float* g4   = (const float*)d_in[16];
    const float* be4  = (const float*)d_in[17];
    const float* u3a  = (const float*)d_in[18];
    const float* ub3a = (const float*)d_in[19];
    const float* u3b  = (const float*)d_in[20];
    const float* ub3b = (const float*)d_in[21];
    const float* u2a  = (const float*)d_in[22];
    const float* ub2a = (const float*)d_in[23];
    const float* u2b  = (const float*)d_in[24];
    const float* ub2b = (const float*)d_in[25];
    const float* u1a  = (const float*)d_in[26];
    const float* ub1a = (const float*)d_in[27];
    const float* u1b  = (const float*)d_in[28];
    const float* ub1b = (const float*)d_in[29];
    const float* wl   = (const float*)d_in[30];
    const float* bl   = (const float*)d_in[31];

    void *pa, *pb, *pc1, *pc2, *pc3, *pbs, *pbb;
    cudaGetSymbolAddress(&pa,  g_SA);
    cudaGetSymbolAddress(&pb,  g_SB);
    cudaGetSymbolAddress(&pc1, g_C1);
    cudaGetSymbolAddress(&pc2, g_C2);
    cudaGetSymbolAddress(&pc3, g_C3);
    cudaGetSymbolAddress(&pbs, g_BNscale);
    cudaGetSymbolAddress(&pbb, g_BNshift);
    float* SA  = (float*)pa;
    float* SB  = (float*)pb;
    float* C1  = (float*)pc1;
    float* C2  = (float*)pc2;
    float* C3  = (float*)pc3;
    float* BNS = (float*)pbs;
    float* BNB = (float*)pbb;

    // --- Encoder ---
    dyn_conv_mish<<<dim3(16, 16, 4), 256>>>(X, W, SA);

    {   // d1: K=4, pad=2, 255->256 + mish -> C1 (4,32,256,256)
        dim3 g((256 / 8) * (256 / 16), 1, 4);
        conv_mish_kernel<4><<<g, 128>>>(SA, d1w, d1b, C1, 32, 255, 255, 32, 256, 256, 2);
    }

    maxpool_kernel<<<cdiv(4 * 32 * 128 * 128, 256), 256>>>(C1, SB, 4 * 32, 256, 256);

    conv3(SB, w2a, b2a, SA, 32, 128, 128);
    conv3(SA, w2b, b2b, C2, 128, 128, 128);

    maxpool_kernel<<<cdiv(4 * 128 * 64 * 64, 256), 256>>>(C2, SA, 4 * 128, 128, 128);

    conv3(SA, w3a, b3a, SB, 128, 64, 256);
    conv3(SB, w3b, b3b, C3, 256, 64, 256);

    maxpool_kernel<<<cdiv(4 * 256 * 32 * 32, 256), 256>>>(C3, SA, 4 * 256, 64, 64);

    conv3(SA, w4a, b4a, SB, 256, 32, 512);
    conv3(SB, w4b, b4b, SA, 512, 32, 512);

    bn_stats_kernel<<<512, 256>>>(SA, g4, be4, BNS, BNB);

    // --- Decoder ---
    up2_kernel<<<cdiv(4 * 512 * 64 * 64, 256), 256>>>(SA, SB, 512, 32, 32, 768, 0, BNS, BNB);
    concat_copy<<<cdiv(4 * 256 * (64 * 64 / 4), 256), 256>>>((const float4*)C3, SB, 256, 64 * 64, 768, 512);

    conv3(SB, u3a, ub3a, SA, 768, 64, 256);
    conv3(SA, u3b, ub3b, SB, 256, 64, 256);

    up2_kernel<<<cdiv(4 * 256 * 128 * 128, 256), 256>>>(SB, SA, 256, 64, 64, 384, 0, nullptr, nullptr);
    concat_copy<<<cdiv(4 * 128 * (128 * 128 / 4), 256), 256>>>((const float4*)C2, SA, 128, 128 * 128, 384, 256);

    conv3(SA, u2a, ub2a, SB, 384, 128, 128);
    conv3(SB, u2b, ub2b, SA, 128, 128, 128);

    up2_kernel<<<cdiv(4 * 128 * 256 * 256, 256), 256>>>(SA, SB, 128, 128, 128, 160, 0, nullptr, nullptr);
    concat_copy<<<cdiv(4 * 32 * (256 * 256 / 4), 256), 256>>>((const float4*)C1, SB, 32, 256 * 256, 160, 128);

    conv3(SB, u1a, ub1a, SA, 160, 256, 32);
    conv3(SA, u1b, ub1b, SB, 32, 256, 32);

    conv1x1_out<<<cdiv(4 * 65536, 256), 256>>>(SB, wl, bl, (float*)d_out);
}

// round 9
// speedup vs baseline: 1.2442x; 1.2442x over previous
#include <cuda_runtime.h>
#include <math.h>

// ---------------------------------------------------------------------------
// Static device scratch (ping-pong A/B + persistent skip buffers).
// ---------------------------------------------------------------------------
__device__ float g_SA[25165824];
__device__ float g_SB[41943040];
__device__ float g_C1[8388608];   // (4,32,256,256)
__device__ float g_C2[8388608];   // (4,128,128,128)
__device__ float g_C3[4194304];   // (4,256,64,64)
__device__ float g_BNscale[512];
__device__ float g_BNshift[512];

static inline int cdiv(int a, int b) { return (a + b - 1) / b; }

__device__ __forceinline__ float mishf(float x) {
    float sp = fmaxf(x, 0.f) + log1pf(expf(-fabsf(x)));
    return x * tanhf(sp);
}

__device__ __forceinline__ unsigned smem_u32(const void* p) {
    return (unsigned)__cvta_generic_to_shared(p);
}
__device__ __forceinline__ void cpa16(unsigned d, const void* s) {
    asm volatile("cp.async.ca.shared.global [%0], [%1], 16;" :: "r"(d), "l"(s));
}
__device__ __forceinline__ void cpa4z(unsigned d, const void* s, int sz) {
    asm volatile("cp.async.ca.shared.global [%0], [%1], 4, %2;" :: "r"(d), "l"(s), "r"(sz));
}

// ---------------------------------------------------------------------------
// Generic direct conv + bias + mish, cp.async double-buffered.
// Block: 128 threads -> 32 output channels x (8 rows x 16 cols) tile, 1 batch.
// Requires: Ci % 8 == 0, Co % 32 == 0, Ho % 8 == 0, Wo % 16 == 0.
// Inner compute loop identical to the R2 baseline (scalar broadcast-friendly
// LDS); global->shared loads for chunk c+1 overlap compute of chunk c.
// ---------------------------------------------------------------------------
template<int K>
__global__ __launch_bounds__(128)
void conv_mish_kernel(const float* __restrict__ in, const float* __restrict__ wt,
                      const float* __restrict__ bias, float* __restrict__ out,
                      int Ci, int Hi, int Wi, int Co, int Ho, int Wo, int pad)
{
    constexpr int K2    = K * K;
    constexpr int CI_CH = 8;
    constexpr int CO_T  = 32;
    constexpr int TH    = 8;
    constexpr int TW    = 16;
    constexpr int XH    = TH + K - 1;
    constexpr int XW    = TW + K - 1;
    constexpr int PER   = CI_CH * K2;          // weight floats per co per chunk
    constexpr int WSZ   = CO_T * PER;          // weight floats per chunk
    constexpr int XS    = CI_CH * XH * XW;     // input floats per chunk

    __shared__ float ws[2][WSZ];
    __shared__ float xs[2][XS];

    const int b   = blockIdx.z;
    const int co0 = blockIdx.y * CO_T;
    const int ntx = Wo / TW;
    const int ty  = blockIdx.x / ntx;
    const int tx  = blockIdx.x - ty * ntx;
    const int y0  = ty * TH;
    const int x0  = tx * TW;

    const int tid = threadIdx.x;
    const int cog = tid >> 4;              // 0..7 -> co_local = cog*4
    const int pg  = tid & 15;
    const int r   = pg >> 1;               // row within tile (0..7)
    const int c0  = (pg & 1) * 8;          // col base within tile (0 or 8)

    float acc[4][8];
#pragma unroll
    for (int a = 0; a < 4; a++)
#pragma unroll
        for (int p = 0; p < 8; p++) acc[a][p] = 0.f;

    const float* inb = in + (size_t)b * Ci * Hi * Wi;
    const size_t HiWi = (size_t)Hi * Wi;

    // ---- async load of one ci-chunk into buffer `buf` ----
    auto load_chunk = [&](int ci0, int buf) {
        // weights: [co][ci0*K2 .. +PER) contiguous, 16B-aligned -> cp.async 16B
#pragma unroll
        for (int i4 = tid; i4 < WSZ / 4; i4 += 128) {
            int co  = i4 / (PER / 4);
            int r4  = i4 - co * (PER / 4);
            const float* src = wt + (size_t)(co0 + co) * Ci * K2
                                  + (size_t)ci0 * K2 + r4 * 4;
            cpa16(smem_u32(&ws[buf][co * PER + r4 * 4]), src);
        }
        // input tile with halo: 4B cp.async, zero-fill when out of bounds
#pragma unroll
        for (int idx = tid; idx < XS; idx += 128) {
            int ci  = idx / (XH * XW);
            int rem = idx - ci * (XH * XW);
            int yy  = rem / XW;
            int xx  = rem - yy * XW;
            int gy  = y0 - pad + yy;
            int gx  = x0 - pad + xx;
            bool ok = (gy >= 0 && gy < Hi && gx >= 0 && gx < Wi);
            const float* src = ok ? (inb + (size_t)(ci0 + ci) * HiWi
                                         + (size_t)gy * Wi + gx)
                                  : inb;
            cpa4z(smem_u32(&xs[buf][idx]), src, ok ? 4 : 0);
        }
    };

    const int nchunks = Ci / CI_CH;
    load_chunk(0, 0);
    asm volatile("cp.async.commit_group;");

    for (int c = 0; c < nchunks; c++) {
        const int buf = c & 1;
        if (c + 1 < nchunks) {
            load_chunk((c + 1) * CI_CH, buf ^ 1);
            asm volatile("cp.async.commit_group;");
            asm volatile("cp.async.wait_group 1;");
        } else {
            asm volatile("cp.async.wait_group 0;");
        }
        __syncthreads();

        const float* wsb = ws[buf];
        const float* xsb = xs[buf];
#pragma unroll
        for (int ci = 0; ci < CI_CH; ci++) {
            const float* wb = &wsb[(cog * 4) * PER + ci * K2];
            const float* xb = &xsb[ci * XH * XW];
#pragma unroll
            for (int i = 0; i < K; i++) {
                float xr[8 + K - 1];
                const float* xp = xb + (r + i) * XW + c0;
#pragma unroll
                for (int t = 0; t < 8 + K - 1; t++) xr[t] = xp[t];
#pragma unroll
                for (int j = 0; j < K; j++) {
                    float w0 = wb[i * K + j];
                    float w1 = wb[PER     + i * K + j];
                    float w2 = wb[2 * PER + i * K + j];
                    float w3 = wb[3 * PER + i * K + j];
#pragma unroll
                    for (int p = 0; p < 8; p++) {
                        float xv = xr[j + p];
                        acc[0][p] = fmaf(w0, xv, acc[0][p]);
                        acc[1][p] = fmaf(w1, xv, acc[1][p]);
                        acc[2][p] = fmaf(w2, xv, acc[2][p]);
                        acc[3][p] = fmaf(w3, xv, acc[3][p]);
                    }
                }
            }
        }
        __syncthreads();
    }

#pragma unroll
    for (int a = 0; a < 4; a++) {
        int co   = co0 + cog * 4 + a;
        float bv = bias[co];
        float* op = out + ((size_t)b * Co + co) * Ho * Wo
                        + (size_t)(y0 + r) * Wo + x0 + c0;
#pragma unroll
        for (int p = 0; p < 8; p++)
            op[p] = mishf(acc[a][p] + bv);
    }
}

// ---------------------------------------------------------------------------
// Per-sample dynamic conv (Ci=1, K=4, pad=1) + mish. x:(4,1,256,256),
// w:(4,32,4,4) -> out:(4,32,255,255).
// ---------------------------------------------------------------------------
__global__ __launch_bounds__(256)
void dyn_conv_mish(const float* __restrict__ x, const float* __restrict__ w,
                   float* __restrict__ out)
{
    const int H = 256, HO = 255;
    __shared__ float ws[32 * 16];
    __shared__ float xs[19][19];

    int b  = blockIdx.z;
    int y0 = blockIdx.y * 16;
    int x0 = blockIdx.x * 16;
    int tid = threadIdx.x;

    for (int i = tid; i < 512; i += 256) ws[i] = w[b * 512 + i];
    for (int i = tid; i < 19 * 19; i += 256) {
        int yy = i / 19, xx = i - yy * 19;
        int gy = y0 - 1 + yy, gx = x0 - 1 + xx;
        xs[yy][xx] = (gy >= 0 && gy < H && gx >= 0 && gx < H)
                     ? x[(size_t)b * H * H + (size_t)gy * H + gx] : 0.f;
    }
    __syncthreads();

    int r  = tid >> 4;
    int cl = tid & 15;
    int oy = y0 + r, ox = x0 + cl;
    if (oy >= HO || ox >= HO) return;

    float xr[16];
#pragma unroll
    for (int i = 0; i < 4; i++)
#pragma unroll
        for (int j = 0; j < 4; j++) xr[i * 4 + j] = xs[r + i][cl + j];

    float* op = out + (size_t)b * 32 * HO * HO + (size_t)oy * HO + ox;
#pragma unroll
    for (int co = 0; co < 32; co++) {
        float a = 0.f;
#pragma unroll
        for (int t = 0; t < 16; t++) a = fmaf(xr[t], ws[co * 16 + t], a);
        op[(size_t)co * HO * HO] = mishf(a);
    }
}

// ---------------------------------------------------------------------------
__global__ void maxpool_kernel(const float* __restrict__ in, float* __restrict__ out,
                               int BC, int Hi, int Wi)
{
    int Ho = Hi >> 1, Wo = Wi >> 1;
    int total = BC * Ho * Wo;
    int n = blockIdx.x * blockDim.x + threadIdx.x;
    if (n >= total) return;
    int xw = n % Wo; int t = n / Wo;
    int y  = t % Ho; int bc = t / Ho;
    const float* p = in + ((size_t)bc * Hi + 2 * y) * Wi + 2 * xw;
    out[n] = fmaxf(fmaxf(p[0], p[1]), fmaxf(p[Wi], p[Wi + 1]));
}

// ---------------------------------------------------------------------------
// Bilinear x2 upsample, align_corners=True, optional per-channel affine (BN),
// writes into channel-offset region of a concat buffer.
// ---------------------------------------------------------------------------
__global__ void up2_kernel(const float* __restrict__ in, float* __restrict__ out,
                           int C, int H, int W, int dstC, int coff,
                           const float* __restrict__ scale,
                           const float* __restrict__ shift)
{
    int Ho = 2 * H, Wo = 2 * W;
    long long total = (long long)4 * C * Ho * Wo;
    long long n = (long long)blockIdx.x * blockDim.x + threadIdx.x;
    if (n >= total) return;
    int ox = (int)(n % Wo); long long t = n / Wo;
    int oy = (int)(t % Ho); t /= Ho;
    int c  = (int)(t % C);  int b = (int)(t / C);

    float ry = (float)((double)(H - 1) / (double)(2 * H - 1));
    float rx = (float)((double)(W - 1) / (double)(2 * W - 1));
    float sy = (float)oy * ry;
    float sx = (float)ox * rx;
    int y0i = (int)sy;
    int x0i = (int)sx;
    float fy = sy - (float)y0i;
    float fx = sx - (float)x0i;
    int y1i = min(y0i + 1, H - 1);
    int x1i = min(x0i + 1, W - 1);

    const float* p = in + ((size_t)b * C + c) * H * W;
    float a0 = p[(size_t)y0i * W + x0i] * (1.f - fy) + p[(size_t)y1i * W + x0i] * fy;
    float a1 = p[(size_t)y0i * W + x1i] * (1.f - fy) + p[(size_t)y1i * W + x1i] * fy;
    float v  = a0 * (1.f - fx) + a1 * fx;
    if (scale) v = v * scale[c] + shift[c];
    out[((size_t)(b * dstC + coff + c) * Ho + oy) * Wo + ox] = v;
}

// ---------------------------------------------------------------------------
__global__ void concat_copy(const float4* __restrict__ src, float* __restrict__ dst,
                            int C, int HW, int dstC, int coff)
{
    int HW4 = HW >> 2;
    int total = 4 * C * HW4;
    int n = blockIdx.x * blockDim.x + threadIdx.x;
    if (n >= total) return;
    int i = n % HW4; int t = n / HW4;
    int c = t % C;   int b = t / C;
    ((float4*)(dst + (size_t)(b * dstC + coff + c) * HW))[i] = src[n];
}

// ---------------------------------------------------------------------------
// BatchNorm batch-stats -> per-channel affine (scale, shift), two-pass.
// ---------------------------------------------------------------------------
__global__ __launch_bounds__(256)
void bn_stats_kernel(const float* __restrict__ h, const float* __restrict__ g,
                     const float* __restrict__ be, float* __restrict__ scale,
                     float* __restrict__ shift)
{
    __shared__ float red[256];
    int c   = blockIdx.x;
    int tid = threadIdx.x;

    float s = 0.f;
    for (int b = 0; b < 4; b++) {
        const float* p = h + ((size_t)b * 512 + c) * 1024;
        for (int i = tid; i < 1024; i += 256) s += p[i];
    }
    red[tid] = s; __syncthreads();
    for (int o = 128; o > 0; o >>= 1) {
        if (tid < o) red[tid] += red[tid + o];
        __syncthreads();
    }
    float mean = red[0] * (1.f / 4096.f);
    __syncthreads();

    float q = 0.f;
    for (int b = 0; b < 4; b++) {
        const float* p = h + ((size_t)b * 512 + c) * 1024;
        for (int i = tid; i < 1024; i += 256) { float d = p[i] - mean; q += d * d; }
    }
    red[tid] = q; __syncthreads();
    for (int o = 128; o > 0; o >>= 1) {
        if (tid < o) red[tid] += red[tid + o];
        __syncthreads();
    }
    if (tid == 0) {
        float var = red[0] * (1.f / 4096.f);
        float sc  = g[c] * rsqrtf(var + 1e-5f);
        scale[c] = sc;
        shift[c] = be[c] - mean * sc;
    }
}

// ---------------------------------------------------------------------------
// Final 1x1 conv, Co=1, no activation.
// ---------------------------------------------------------------------------
__global__ void conv1x1_out(const float* __restrict__ in, const float* __restrict__ wl,
                            const float* __restrict__ bl, float* __restrict__ out)
{
    __shared__ float w[32];
    if (threadIdx.x < 32) w[threadIdx.x] = wl[threadIdx.x];
    __syncthreads();
    int n = blockIdx.x * blockDim.x + threadIdx.x;
    if (n >= 4 * 65536) return;
    int b = n >> 16;
    int i = n & 65535;
    const float* p = in + (size_t)b * 32 * 65536 + i;
    float s = bl[0];
#pragma unroll
    for (int c = 0; c < 32; c++) s = fmaf(p[(size_t)c * 65536], w[c], s);
    out[n] = s;
}

// ---------------------------------------------------------------------------
// Host side
// ---------------------------------------------------------------------------
static void conv3(const float* in, const float* wt, const float* bs, float* out,
                  int Ci, int HW, int Co)
{
    dim3 g((HW / 8) * (HW / 16), Co / 32, 4);
    conv_mish_kernel<3><<<g, 128>>>(in, wt, bs, out, Ci, HW, HW, Co, HW, HW, 1);
}

extern "C" void kernel_launch(void* const* d_in, const int* in_sizes, int n_in,
                              void* d_out, int out_size)
{
    const float* X    = (const float*)d_in[0];
    const float* W    = (const float*)d_in[1];
    const float* d1w  = (const float*)d_in[2];
    const float* d1b  = (const float*)d_in[3];
    const float* w2a  = (const float*)d_in[4];
    const float* b2a  = (const float*)d_in[5];
    const float* w2b  = (const float*)d_in[6];
    const float* b2b  = (const float*)d_in[7];
    const float* w3a  = (const float*)d_in[8];
    const float* b3a  = (const float*)d_in[9];
    const float* w3b  = (const float*)d_in[10];
    const float* b3b  = (const float*)d_in[11];
    const float* w4a  = (const float*)d_in[12];
    const float* b4a  = (const float*)d_in[13];
    const float* w4b  = (const float*)d_in[14];
    const float* b4b  = (const float*)d_in[15];
    const float* g4   = (const float*)d_in[16];
    const float* be4  = (const float*)d_in[17];
    const float* u3a  = (const float*)d_in[18];
    const float* ub3a = (const float*)d_in[19];
    const float* u3b  = (const float*)d_in[20];
    const float* ub3b = (const float*)d_in[21];
    const float* u2a  = (const float*)d_in[22];
    const float* ub2a = (const float*)d_in[23];
    const float* u2b  = (const float*)d_in[24];
    const float* ub2b = (const float*)d_in[25];
    const float* u1a  = (const float*)d_in[26];
    const float* ub1a = (const float*)d_in[27];
    const float* u1b  = (const float*)d_in[28];
    const float* ub1b = (const float*)d_in[29];
    const float* wl   = (const float*)d_in[30];
    const float* bl   = (const float*)d_in[31];

    void *pa, *pb, *pc1, *pc2, *pc3, *pbs, *pbb;
    cudaGetSymbolAddress(&pa,  g_SA);
    cudaGetSymbolAddress(&pb,  g_SB);
    cudaGetSymbolAddress(&pc1, g_C1);
    cudaGetSymbolAddress(&pc2, g_C2);
    cudaGetSymbolAddress(&pc3, g_C3);
    cudaGetSymbolAddress(&pbs, g_BNscale);
    cudaGetSymbolAddress(&pbb, g_BNshift);
    float* SA  = (float*)pa;
    float* SB  = (float*)pb;
    float* C1  = (float*)pc1;
    float* C2  = (float*)pc2;
    float* C3  = (float*)pc3;
    float* BNS = (float*)pbs;
    float* BNB = (float*)pbb;

    // --- Encoder ---
    dyn_conv_mish<<<dim3(16, 16, 4), 256>>>(X, W, SA);

    {   // d1: K=4, pad=2, 255->256 + mish -> C1 (4,32,256,256)
        dim3 g((256 / 8) * (256 / 16), 1, 4);
        conv_mish_kernel<4><<<g, 128>>>(SA, d1w, d1b, C1, 32, 255, 255, 32, 256, 256, 2);
    }

    maxpool_kernel<<<cdiv(4 * 32 * 128 * 128, 256), 256>>>(C1, SB, 4 * 32, 256, 256);

    conv3(SB, w2a, b2a, SA, 32, 128, 128);
    conv3(SA, w2b, b2b, C2, 128, 128, 128);

    maxpool_kernel<<<cdiv(4 * 128 * 64 * 64, 256), 256>>>(C2, SA, 4 * 128, 128, 128);

    conv3(SA, w3a, b3a, SB, 128, 64, 256);
    conv3(SB, w3b, b3b, C3, 256, 64, 256);

    maxpool_kernel<<<cdiv(4 * 256 * 32 * 32, 256), 256>>>(C3, SA, 4 * 256, 64, 64);

    conv3(SA, w4a, b4a, SB, 256, 32, 512);
    conv3(SB, w4b, b4b, SA, 512, 32, 512);

    bn_stats_kernel<<<512, 256>>>(SA, g4, be4, BNS, BNB);

    // --- Decoder ---
    up2_kernel<<<cdiv(4 * 512 * 64 * 64, 256), 256>>>(SA, SB, 512, 32, 32, 768, 0, BNS, BNB);
    concat_copy<<<cdiv(4 * 256 * (64 * 64 / 4), 256), 256>>>((const float4*)C3, SB, 256, 64 * 64, 768, 512);

    conv3(SB, u3a, ub3a, SA, 768, 64, 256);
    conv3(SA, u3b, ub3b, SB, 256, 64, 256);

    up2_kernel<<<cdiv(4 * 256 * 128 * 128, 256), 256>>>(SB, SA, 256, 64, 64, 384, 0, nullptr, nullptr);
    concat_copy<<<cdiv(4 * 128 * (128 * 128 / 4), 256), 256>>>((const float4*)C2, SA, 128, 128 * 128, 384, 256);

    conv3(SA, u2a, ub2a, SB, 384, 128, 128);
    conv3(SB, u2b, ub2b, SA, 128, 128, 128);

    up2_kernel<<<cdiv(4 * 128 * 256 * 256, 256), 256>>>(SA, SB, 128, 128, 128, 160, 0, nullptr, nullptr);
    concat_copy<<<cdiv(4 * 32 * (256 * 256 / 4), 256), 256>>>((const float4*)C1, SB, 32, 256 * 256, 160, 128);

    conv3(SB, u1a, ub1a, SA, 160, 256, 32);
    conv3(SA, u1b, ub1b, SB, 32, 256, 32);

    conv1x1_out<<<cdiv(4 * 65536, 256), 256>>>(SB, wl, bl, (float*)d_out);
}

// round 12
// speedup vs baseline: 1.3557x; 1.0896x over previous
#include <cuda_runtime.h>
#include <math.h>

// ---------------------------------------------------------------------------
// Static device scratch (ping-pong A/B + persistent skip buffers).
// ---------------------------------------------------------------------------
__device__ float g_SA[25165824];
__device__ float g_SB[41943040];
__device__ float g_C1[8388608];   // (4,32,256,256)
__device__ float g_C2[8388608];   // (4,128,128,128)
__device__ float g_C3[4194304];   // (4,256,64,64)
__device__ float g_BNscale[512];
__device__ float g_BNshift[512];

static inline int cdiv(int a, int b) { return (a + b - 1) / b; }

__device__ __forceinline__ float mishf(float x) {
    float sp = fmaxf(x, 0.f) + log1pf(expf(-fabsf(x)));
    return x * tanhf(sp);
}

__device__ __forceinline__ unsigned smem_u32(const void* p) {
    return (unsigned)__cvta_generic_to_shared(p);
}
__device__ __forceinline__ void cpa16(unsigned d, const void* s) {
    asm volatile("cp.async.ca.shared.global [%0], [%1], 16;" :: "r"(d), "l"(s));
}
__device__ __forceinline__ void cpa4z(unsigned d, const void* s, int sz) {
    asm volatile("cp.async.ca.shared.global [%0], [%1], 4, %2;" :: "r"(d), "l"(s), "r"(sz));
}

// ---------------------------------------------------------------------------
// Generic direct conv + bias + mish, cp.async double-buffered with HOISTED
// load state: per-thread src pointers/predicates computed once, advanced by
// constant strides per chunk (input: +Hi*Wi per ci; weights: +CI_CH*K2 per
// chunk). Register diet via __launch_bounds__(128,5) -> 5 blocks/SM.
// Block: 128 threads -> 32 co x (8x16 px), 1 batch.
// Requires: Ci % 8 == 0, Co % 32 == 0, Ho % 8 == 0, Wo % 16 == 0.
// ---------------------------------------------------------------------------
template<int K>
__global__ __launch_bounds__(128, 5)
void conv_mish_kernel(const float* __restrict__ in, const float* __restrict__ wt,
                      const float* __restrict__ bias, float* __restrict__ out,
                      int Ci, int Hi, int Wi, int Co, int Ho, int Wo, int pad)
{
    constexpr int K2    = K * K;
    constexpr int CI_CH = 8;
    constexpr int CO_T  = 32;
    constexpr int TH    = 8;
    constexpr int TW    = 16;
    constexpr int XH    = TH + K - 1;
    constexpr int XW    = TW + K - 1;
    constexpr int TILE  = XH * XW;             // 180 (K=3) / 209 (K=4)
    constexpr int PER   = CI_CH * K2;          // weight floats per co per chunk
    constexpr int WSZ   = CO_T * PER;          // weight floats per chunk
    constexpr int WSZ4  = WSZ / 4;             // vec4 count
    constexpr int XS    = CI_CH * TILE;        // input floats per chunk
    constexpr int NW    = (WSZ4 + 127) / 128;  // weight vec4 slots per thread
    constexpr int NX    = (TILE + 127) / 128;  // input position slots per thread

    __shared__ float ws[2][WSZ];
    __shared__ float xs[2][XS];

    const int b   = blockIdx.z;
    const int co0 = blockIdx.y * CO_T;
    const int ntx = Wo / TW;
    const int ty  = blockIdx.x / ntx;
    const int tx  = blockIdx.x - ty * ntx;
    const int y0  = ty * TH;
    const int x0  = tx * TW;

    const int tid = threadIdx.x;
    const int cog = tid >> 4;              // 0..7 -> co_local = cog*4
    const int pg  = tid & 15;
    const int r   = pg >> 1;               // row within tile (0..7)
    const int c0  = (pg & 1) * 8;          // col base within tile (0 or 8)

    const float* inb  = in + (size_t)b * Ci * Hi * Wi;
    const size_t HiWi = (size_t)Hi * Wi;

    // ---- hoisted per-thread load state (constant strides per chunk) ----
    const float* wptr[NW];
#pragma unroll
    for (int s = 0; s < NW; s++) {
        if (s < WSZ4 / 128 || tid < (WSZ4 & 127)) {
            int v  = tid + s * 128;
            int co = v / (PER / 4);
            int r4 = v - co * (PER / 4);
            wptr[s] = wt + (size_t)(co0 + co) * Ci * K2 + r4 * 4;
        }
    }
    const float* xptr[NX];
    int xsz[NX];
#pragma unroll
    for (int s = 0; s < NX; s++) {
        int pos = tid + s * 128;
        int yy  = pos / XW;
        int xx  = pos - yy * XW;
        int gy  = y0 - pad + yy;
        int gx  = x0 - pad + xx;
        bool ok = (pos < TILE) && gy >= 0 && gy < Hi && gx >= 0 && gx < Wi;
        xptr[s] = ok ? (inb + (size_t)gy * Wi + gx) : inb;
        xsz[s]  = ok ? 4 : 0;
    }
    const unsigned wsb = smem_u32(&ws[0][0]);
    const unsigned xsb = smem_u32(&xs[0][0]);

    float acc[4][8];
#pragma unroll
    for (int a = 0; a < 4; a++)
#pragma unroll
        for (int p = 0; p < 8; p++) acc[a][p] = 0.f;

    // ---- async issue of one ci-chunk into buffer `buf` ----
    auto issue = [&](int buf) {
#pragma unroll
        for (int s = 0; s < NW; s++) {
            if (s < WSZ4 / 128 || tid < (WSZ4 & 127)) {
                cpa16(wsb + buf * (WSZ * 4) + (tid + s * 128) * 16, wptr[s]);
                wptr[s] += PER;
            }
        }
#pragma unroll
        for (int s = 0; s < NX; s++) {
            if (s < TILE / 128 || tid < (TILE & 127)) {
                unsigned d = xsb + buf * (XS * 4) + (tid + s * 128) * 4;
                const float* p = xptr[s];
#pragma unroll
                for (int ci = 0; ci < CI_CH; ci++) {
                    cpa4z(d + ci * (TILE * 4), p, xsz[s]);
                    p += HiWi;
                }
                xptr[s] = p;
            }
        }
    };

    const int nchunks = Ci / CI_CH;
    issue(0);
    asm volatile("cp.async.commit_group;");

    for (int c = 0; c < nchunks; c++) {
        const int buf = c & 1;
        if (c + 1 < nchunks) {
            issue(buf ^ 1);
            asm volatile("cp.async.commit_group;");
            asm volatile("cp.async.wait_group 1;");
        } else {
            asm volatile("cp.async.wait_group 0;");
        }
        __syncthreads();

        const float* wsc = ws[buf];
        const float* xsc = xs[buf];
#pragma unroll
        for (int ci = 0; ci < CI_CH; ci++) {
            const float* wb = &wsc[(cog * 4) * PER + ci * K2];
            const float* xb = &xsc[ci * TILE];
#pragma unroll
            for (int i = 0; i < K; i++) {
                float xr[8 + K - 1];
                const float* xp = xb + (r + i) * XW + c0;
#pragma unroll
                for (int t = 0; t < 8 + K - 1; t++) xr[t] = xp[t];
#pragma unroll
                for (int j = 0; j < K; j++) {
                    float w0 = wb[i * K + j];
                    float w1 = wb[PER     + i * K + j];
                    float w2 = wb[2 * PER + i * K + j];
                    float w3 = wb[3 * PER + i * K + j];
#pragma unroll
                    for (int p = 0; p < 8; p++) {
                        float xv = xr[j + p];
                        acc[0][p] = fmaf(w0, xv, acc[0][p]);
                        acc[1][p] = fmaf(w1, xv, acc[1][p]);
                        acc[2][p] = fmaf(w2, xv, acc[2][p]);
                        acc[3][p] = fmaf(w3, xv, acc[3][p]);
                    }
                }
            }
        }
        __syncthreads();
    }

#pragma unroll
    for (int a = 0; a < 4; a++) {
        int co   = co0 + cog * 4 + a;
        float bv = bias[co];
        float* op = out + ((size_t)b * Co + co) * Ho * Wo
                        + (size_t)(y0 + r) * Wo + x0 + c0;
#pragma unroll
        for (int p = 0; p < 8; p++)
            op[p] = mishf(acc[a][p] + bv);
    }
}

// ---------------------------------------------------------------------------
// Per-sample dynamic conv (Ci=1, K=4, pad=1) + mish. x:(4,1,256,256),
// w:(4,32,4,4) -> out:(4,32,255,255).
// ---------------------------------------------------------------------------
__global__ __launch_bounds__(256)
void dyn_conv_mish(const float* __restrict__ x, const float* __restrict__ w,
                   float* __restrict__ out)
{
    const int H = 256, HO = 255;
    __shared__ float ws[32 * 16];
    __shared__ float xs[19][19];

    int b  = blockIdx.z;
    int y0 = blockIdx.y * 16;
    int x0 = blockIdx.x * 16;
    int tid = threadIdx.x;

    for (int i = tid; i < 512; i += 256) ws[i] = w[b * 512 + i];
    for (int i = tid; i < 19 * 19; i += 256) {
        int yy = i / 19, xx = i - yy * 19;
        int gy = y0 - 1 + yy, gx = x0 - 1 + xx;
        xs[yy][xx] = (gy >= 0 && gy < H && gx >= 0 && gx < H)
                     ? x[(size_t)b * H * H + (size_t)gy * H + gx] : 0.f;
    }
    __syncthreads();

    int r  = tid >> 4;
    int cl = tid & 15;
    int oy = y0 + r, ox = x0 + cl;
    if (oy >= HO || ox >= HO) return;

    float xr[16];
#pragma unroll
    for (int i = 0; i < 4; i++)
#pragma unroll
        for (int j = 0; j < 4; j++) xr[i * 4 + j] = xs[r + i][cl + j];

    float* op = out + (size_t)b * 32 * HO * HO + (size_t)oy * HO + ox;
#pragma unroll
    for (int co = 0; co < 32; co++) {
        float a = 0.f;
#pragma unroll
        for (int t = 0; t < 16; t++) a = fmaf(xr[t], ws[co * 16 + t], a);
        op[(size_t)co * HO * HO] = mishf(a);
    }
}

// ---------------------------------------------------------------------------
__global__ void maxpool_kernel(const float* __restrict__ in, float* __restrict__ out,
                               int BC, int Hi, int Wi)
{
    int Ho = Hi >> 1, Wo = Wi >> 1;
    int total = BC * Ho * Wo;
    int n = blockIdx.x * blockDim.x + threadIdx.x;
    if (n >= total) return;
    int xw = n % Wo; int t = n / Wo;
    int y  = t % Ho; int bc = t / Ho;
    const float* p = in + ((size_t)bc * Hi + 2 * y) * Wi + 2 * xw;
    out[n] = fmaxf(fmaxf(p[0], p[1]), fmaxf(p[Wi], p[Wi + 1]));
}

// ---------------------------------------------------------------------------
// Bilinear x2 upsample, align_corners=True, optional per-channel affine (BN),
// writes into channel-offset region of a concat buffer.
// ---------------------------------------------------------------------------
__global__ void up2_kernel(const float* __restrict__ in, float* __restrict__ out,
                           int C, int H, int W, int dstC, int coff,
                           const float* __restrict__ scale,
                           const float* __restrict__ shift)
{
    int Ho = 2 * H, Wo = 2 * W;
    long long total = (long long)4 * C * Ho * Wo;
    long long n = (long long)blockIdx.x * blockDim.x + threadIdx.x;
    if (n >= total) return;
    int ox = (int)(n % Wo); long long t = n / Wo;
    int oy = (int)(t % Ho); t /= Ho;
    int c  = (int)(t % C);  int b = (int)(t / C);

    float ry = (float)((double)(H - 1) / (double)(2 * H - 1));
    float rx = (float)((double)(W - 1) / (double)(2 * W - 1));
    float sy = (float)oy * ry;
    float sx = (float)ox * rx;
    int y0i = (int)sy;
    int x0i = (int)sx;
    float fy = sy - (float)y0i;
    float fx = sx - (float)x0i;
    int y1i = min(y0i + 1, H - 1);
    int x1i = min(x0i + 1, W - 1);

    const float* p = in + ((size_t)b * C + c) * H * W;
    float a0 = p[(size_t)y0i * W + x0i] * (1.f - fy) + p[(size_t)y1i * W + x0i] * fy;
    float a1 = p[(size_t)y0i * W + x1i] * (1.f - fy) + p[(size_t)y1i * W + x1i] * fy;
    float v  = a0 * (1.f - fx) + a1 * fx;
    if (scale) v = v * scale[c] + shift[c];
    out[((size_t)(b * dstC + coff + c) * Ho + oy) * Wo + ox] = v;
}

// ---------------------------------------------------------------------------
__global__ void concat_copy(const float4* __restrict__ src, float* __restrict__ dst,
                            int C, int HW, int dstC, int coff)
{
    int HW4 = HW >> 2;
    int total = 4 * C * HW4;
    int n = blockIdx.x * blockDim.x + threadIdx.x;
    if (n >= total) return;
    int i = n % HW4; int t = n / HW4;
    int c = t % C;   int b = t / C;
    ((float4*)(dst + (size_t)(b * dstC + coff + c) * HW))[i] = src[n];
}

// ---------------------------------------------------------------------------
// BatchNorm batch-stats -> per-channel affine (scale, shift), two-pass.
// ---------------------------------------------------------------------------
__global__ __launch_bounds__(256)
void bn_stats_kernel(const float* __restrict__ h, const float* __restrict__ g,
                     const float* __restrict__ be, float* __restrict__ scale,
                     float* __restrict__ shift)
{
    __shared__ float red[256];
    int c   = blockIdx.x;
    int tid = threadIdx.x;

    float s = 0.f;
    for (int b = 0; b < 4; b++) {
        const float* p = h + ((size_t)b * 512 + c) * 1024;
        for (int i = tid; i < 1024; i += 256) s += p[i];
    }
    red[tid] = s; __syncthreads();
    for (int o = 128; o > 0; o >>= 1) {
        if (tid < o) red[tid] += red[tid + o];
        __syncthreads();
    }
    float mean = red[0] * (1.f / 4096.f);
    __syncthreads();

    float q = 0.f;
    for (int b = 0; b < 4; b++) {
        const float* p = h + ((size_t)b * 512 + c) * 1024;
        for (int i = tid; i < 1024; i += 256) { float d = p[i] - mean; q += d * d; }
    }
    red[tid] = q; __syncthreads();
    for (int o = 128; o > 0; o >>= 1) {
        if (tid < o) red[tid] += red[tid + o];
        __syncthreads();
    }
    if (tid == 0) {
        float var = red[0] * (1.f / 4096.f);
        float sc  = g[c] * rsqrtf(var + 1e-5f);
        scale[c] = sc;
        shift[c] = be[c] - mean * sc;
    }
}

// ---------------------------------------------------------------------------
// Final 1x1 conv, Co=1, no activation.
// ---------------------------------------------------------------------------
__global__ void conv1x1_out(const float* __restrict__ in, const float* __restrict__ wl,
                            const float* __restrict__ bl, float* __restrict__ out)
{
    __shared__ float w[32];
    if (threadIdx.x < 32) w[threadIdx.x] = wl[threadIdx.x];
    __syncthreads();
    int n = blockIdx.x * blockDim.x + threadIdx.x;
    if (n >= 4 * 65536) return;
    int b = n >> 16;
    int i = n & 65535;
    const float* p = in + (size_t)b * 32 * 65536 + i;
    float s = bl[0];
#pragma unroll
    for (int c = 0; c < 32; c++) s = fmaf(p[(size_t)c * 65536], w[c], s);
    out[n] = s;
}

// ---------------------------------------------------------------------------
// Host side
// ---------------------------------------------------------------------------
static void conv3(const float* in, const float* wt, const float* bs, float* out,
                  int Ci, int HW, int Co)
{
    dim3 g((HW / 8) * (HW / 16), Co / 32, 4);
    conv_mish_kernel<3><<<g, 128>>>(in, wt, bs, out, Ci, HW, HW, Co, HW, HW, 1);
}

extern "C" void kernel_launch(void* const* d_in, const int* in_sizes, int n_in,
                              void* d_out, int out_size)
{
    const float* X    = (const float*)d_in[0];
    const float* W    = (const float*)d_in[1];
    const float* d1w  = (const float*)d_in[2];
    const float* d1b  = (const float*)d_in[3];
    const float* w2a  = (const float*)d_in[4];
    const float* b2a  = (const float*)d_in[5];
    const float* w2b  = (const float*)d_in[6];
    const float* b2b  = (const float*)d_in[7];
    const float* w3a  = (const float*)d_in[8];
    const float* b3a  = (const float*)d_in[9];
    const float* w3b  = (const float*)d_in[10];
    const float* b3b  = (const float*)d_in[11];
    const float* w4a  = (const float*)d_in[12];
    const float* b4a  = (const float*)d_in[13];
    const float* w4b  = (const float*)d_in[14];
    const float* b4b  = (const float*)d_in[15];
    const float* g4   = (const float*)d_in[16];
    const float* be4  = (const float*)d_in[17];
    const float* u3a  = (const float*)d_in[18];
    const float* ub3a = (const float*)d_in[19];
    const float* u3b  = (const float*)d_in[20];
    const float* ub3b = (const float*)d_in[21];
    const float* u2a  = (const float*)d_in[22];
    const float* ub2a = (const float*)d_in[23];
    const float* u2b  = (const float*)d_in[24];
    const float* ub2b = (const float*)d_in[25];
    const float* u1a  = (const float*)d_in[26];
    const float* ub1a = (const float*)d_in[27];
    const float* u1b  = (const float*)d_in[28];
    const float* ub1b = (const float*)d_in[29];
    const float* wl   = (const float*)d_in[30];
    const float* bl   = (const float*)d_in[31];

    void *pa, *pb, *pc1, *pc2, *pc3, *pbs, *pbb;
    cudaGetSymbolAddress(&pa,  g_SA);
    cudaGetSymbolAddress(&pb,  g_SB);
    cudaGetSymbolAddress(&pc1, g_C1);
    cudaGetSymbolAddress(&pc2, g_C2);
    cudaGetSymbolAddress(&pc3, g_C3);
    cudaGetSymbolAddress(&pbs, g_BNscale);
    cudaGetSymbolAddress(&pbb, g_BNshift);
    float* SA  = (float*)pa;
    float* SB  = (float*)pb;
    float* C1  = (float*)pc1;
    float* C2  = (float*)pc2;
    float* C3  = (float*)pc3;
    float* BNS = (float*)pbs;
    float* BNB = (float*)pbb;

    // --- Encoder ---
    dyn_conv_mish<<<dim3(16, 16, 4), 256>>>(X, W, SA);

    {   // d1: K=4, pad=2, 255->256 + mish -> C1 (4,32,256,256)
        dim3 g((256 / 8) * (256 / 16), 1, 4);
        conv_mish_kernel<4><<<g, 128>>>(SA, d1w, d1b, C1, 32, 255, 255, 32, 256, 256, 2);
    }

    maxpool_kernel<<<cdiv(4 * 32 * 128 * 128, 256), 256>>>(C1, SB, 4 * 32, 256, 256);

    conv3(SB, w2a, b2a, SA, 32, 128, 128);
    conv3(SA, w2b, b2b, C2, 128, 128, 128);

    maxpool_kernel<<<cdiv(4 * 128 * 64 * 64, 256), 256>>>(C2, SA, 4 * 128, 128, 128);

    conv3(SA, w3a, b3a, SB, 128, 64, 256);
    conv3(SB, w3b, b3b, C3, 256, 64, 256);

    maxpool_kernel<<<cdiv(4 * 256 * 32 * 32, 256), 256>>>(C3, SA, 4 * 256, 64, 64);

    conv3(SA, w4a, b4a, SB, 256, 32, 512);
    conv3(SB, w4b, b4b, SA, 512, 32, 512);

    bn_stats_kernel<<<512, 256>>>(SA, g4, be4, BNS, BNB);

    // --- Decoder ---
    up2_kernel<<<cdiv(4 * 512 * 64 * 64, 256), 256>>>(SA, SB, 512, 32, 32, 768, 0, BNS, BNB);
    concat_copy<<<cdiv(4 * 256 * (64 * 64 / 4), 256), 256>>>((const float4*)C3, SB, 256, 64 * 64, 768, 512);

    conv3(SB, u3a, ub3a, SA, 768, 64, 256);
    conv3(SA, u3b, ub3b, SB, 256, 64, 256);

    up2_kernel<<<cdiv(4 * 256 * 128 * 128, 256), 256>>>(SB, SA, 256, 64, 64, 384, 0, nullptr, nullptr);
    concat_copy<<<cdiv(4 * 128 * (128 * 128 / 4), 256), 256>>>((const float4*)C2, SA, 128, 128 * 128, 384, 256);

    conv3(SA, u2a, ub2a, SB, 384, 128, 128);
    conv3(SB, u2b, ub2b, SA, 128, 128, 128);

    up2_kernel<<<cdiv(4 * 128 * 256 * 256, 256), 256>>>(SA, SB, 128, 128, 128, 160, 0, nullptr, nullptr);
    concat_copy<<<cdiv(4 * 32 * (256 * 256 / 4), 256), 256>>>((const float4*)C1, SB, 32, 256 * 256, 160, 128);

    conv3(SB, u1a, ub1a, SA, 160, 256, 32);
    conv3(SA, u1b, ub1b, SB, 32, 256, 32);

    conv1x1_out<<<cdiv(4 * 65536, 256), 256>>>(SB, wl, bl, (float*)d_out);
}

// round 16
// speedup vs baseline: 1.3567x; 1.0008x over previous
#include <cuda_runtime.h>
#include <math.h>

// ---------------------------------------------------------------------------
// Static device scratch (ping-pong A/B + persistent skip buffers).
// ---------------------------------------------------------------------------
__device__ float g_SA[25165824];
__device__ float g_SB[41943040];
__device__ float g_C1[8388608];   // (4,32,256,256)
__device__ float g_C2[8388608];   // (4,128,128,128)
__device__ float g_C3[4194304];   // (4,256,64,64)
__device__ float g_BNscale[512];
__device__ float g_BNshift[512];

static inline int cdiv(int a, int b) { return (a + b - 1) / b; }

__device__ __forceinline__ float mishf(float x) {
    float sp = fmaxf(x, 0.f) + log1pf(expf(-fabsf(x)));
    return x * tanhf(sp);
}

__device__ __forceinline__ unsigned smem_u32(const void* p) {
    return (unsigned)__cvta_generic_to_shared(p);
}
__device__ __forceinline__ void cpa16(unsigned d, const void* s) {
    asm volatile("cp.async.ca.shared.global [%0], [%1], 16;" :: "r"(d), "l"(s));
}
__device__ __forceinline__ void cpa4z(unsigned d, const void* s, int sz) {
    asm volatile("cp.async.ca.shared.global [%0], [%1], 4, %2;" :: "r"(d), "l"(s), "r"(sz));
}

// ---------------------------------------------------------------------------
// Generic direct conv + bias + mish, cp.async double-buffered with HOISTED
// load state: per-thread src pointers/predicates computed once, advanced by
// constant strides per chunk (input: +Hi*Wi per ci; weights: +CI_CH*K2 per
// chunk). Register diet via __launch_bounds__(128,5) -> 5 blocks/SM.
// Block: 128 threads -> 32 co x (8x16 px), 1 batch.
// Requires: Ci % 8 == 0, Co % 32 == 0, Ho % 8 == 0, Wo % 16 == 0.
// ---------------------------------------------------------------------------
template<int K>
__global__ __launch_bounds__(128, 5)
void conv_mish_kernel(const float* __restrict__ in, const float* __restrict__ wt,
                      const float* __restrict__ bias, float* __restrict__ out,
                      int Ci, int Hi, int Wi, int Co, int Ho, int Wo, int pad)
{
    constexpr int K2    = K * K;
    constexpr int CI_CH = 8;
    constexpr int CO_T  = 32;
    constexpr int TH    = 8;
    constexpr int TW    = 16;
    constexpr int XH    = TH + K - 1;
    constexpr int XW    = TW + K - 1;
    constexpr int TILE  = XH * XW;             // 180 (K=3) / 209 (K=4)
    constexpr int PER   = CI_CH * K2;          // weight floats per co per chunk
    constexpr int WSZ   = CO_T * PER;          // weight floats per chunk
    constexpr int WSZ4  = WSZ / 4;             // vec4 count
    constexpr int XS    = CI_CH * TILE;        // input floats per chunk
    constexpr int NW    = (WSZ4 + 127) / 128;  // weight vec4 slots per thread
    constexpr int NX    = (TILE + 127) / 128;  // input position slots per thread

    __shared__ float ws[2][WSZ];
    __shared__ float xs[2][XS];

    const int b   = blockIdx.z;
    const int co0 = blockIdx.y * CO_T;
    const int ntx = Wo / TW;
    const int ty  = blockIdx.x / ntx;
    const int tx  = blockIdx.x - ty * ntx;
    const int y0  = ty * TH;
    const int x0  = tx * TW;

    const int tid = threadIdx.x;
    const int cog = tid >> 4;              // 0..7 -> co_local = cog*4
    const int pg  = tid & 15;
    const int r   = pg >> 1;               // row within tile (0..7)
    const int c0  = (pg & 1) * 8;          // col base within tile (0 or 8)

    const float* inb  = in + (size_t)b * Ci * Hi * Wi;
    const size_t HiWi = (size_t)Hi * Wi;

    // ---- hoisted per-thread load state (constant strides per chunk) ----
    const float* wptr[NW];
#pragma unroll
    for (int s = 0; s < NW; s++) {
        if (s < WSZ4 / 128 || tid < (WSZ4 & 127)) {
            int v  = tid + s * 128;
            int co = v / (PER / 4);
            int r4 = v - co * (PER / 4);
            wptr[s] = wt + (size_t)(co0 + co) * Ci * K2 + r4 * 4;
        }
    }
    const float* xptr[NX];
    int xsz[NX];
#pragma unroll
    for (int s = 0; s < NX; s++) {
        int pos = tid + s * 128;
        int yy  = pos / XW;
        int xx  = pos - yy * XW;
        int gy  = y0 - pad + yy;
        int gx  = x0 - pad + xx;
        bool ok = (pos < TILE) && gy >= 0 && gy < Hi && gx >= 0 && gx < Wi;
        xptr[s] = ok ? (inb + (size_t)gy * Wi + gx) : inb;
        xsz[s]  = ok ? 4 : 0;
    }
    const unsigned wsb = smem_u32(&ws[0][0]);
    const unsigned xsb = smem_u32(&xs[0][0]);

    float acc[4][8];
#pragma unroll
    for (int a = 0; a < 4; a++)
#pragma unroll
        for (int p = 0; p < 8; p++) acc[a][p] = 0.f;

    // ---- async issue of one ci-chunk into buffer `buf` ----
    auto issue = [&](int buf) {
#pragma unroll
        for (int s = 0; s < NW; s++) {
            if (s < WSZ4 / 128 || tid < (WSZ4 & 127)) {
                cpa16(wsb + buf * (WSZ * 4) + (tid + s * 128) * 16, wptr[s]);
                wptr[s] += PER;
            }
        }
#pragma unroll
        for (int s = 0; s < NX; s++) {
            if (s < TILE / 128 || tid < (TILE & 127)) {
                unsigned d = xsb + buf * (XS * 4) + (tid + s * 128) * 4;
                const float* p = xptr[s];
#pragma unroll
                for (int ci = 0; ci < CI_CH; ci++) {
                    cpa4z(d + ci * (TILE * 4), p, xsz[s]);
                    p += HiWi;
                }
                xptr[s] = p;
            }
        }
    };

    const int nchunks = Ci / CI_CH;
    issue(0);
    asm volatile("cp.async.commit_group;");

    for (int c = 0; c < nchunks; c++) {
        const int buf = c & 1;
        if (c + 1 < nchunks) {
            issue(buf ^ 1);
            asm volatile("cp.async.commit_group;");
            asm volatile("cp.async.wait_group 1;");
        } else {
            asm volatile("cp.async.wait_group 0;");
        }
        __syncthreads();

        const float* wsc = ws[buf];
        const float* xsc = xs[buf];
#pragma unroll
        for (int ci = 0; ci < CI_CH; ci++) {
            const float* wb = &wsc[(cog * 4) * PER + ci * K2];
            const float* xb = &xsc[ci * TILE];
#pragma unroll
            for (int i = 0; i < K; i++) {
                float xr[8 + K - 1];
                const float* xp = xb + (r + i) * XW + c0;
#pragma unroll
                for (int t = 0; t < 8 + K - 1; t++) xr[t] = xp[t];
#pragma unroll
                for (int j = 0; j < K; j++) {
                    float w0 = wb[i * K + j];
                    float w1 = wb[PER     + i * K + j];
                    float w2 = wb[2 * PER + i * K + j];
                    float w3 = wb[3 * PER + i * K + j];
#pragma unroll
                    for (int p = 0; p < 8; p++) {
                        float xv = xr[j + p];
                        acc[0][p] = fmaf(w0, xv, acc[0][p]);
                        acc[1][p] = fmaf(w1, xv, acc[1][p]);
                        acc[2][p] = fmaf(w2, xv, acc[2][p]);
                        acc[3][p] = fmaf(w3, xv, acc[3][p]);
                    }
                }
            }
        }
        __syncthreads();
    }

#pragma unroll
    for (int a = 0; a < 4; a++) {
        int co   = co0 + cog * 4 + a;
        float bv = bias[co];
        float* op = out + ((size_t)b * Co + co) * Ho * Wo
                        + (size_t)(y0 + r) * Wo + x0 + c0;
#pragma unroll
        for (int p = 0; p < 8; p++)
            op[p] = mishf(acc[a][p] + bv);
    }
}

// ---------------------------------------------------------------------------
// Per-sample dynamic conv (Ci=1, K=4, pad=1) + mish. x:(4,1,256,256),
// w:(4,32,4,4) -> out:(4,32,255,255).
// ---------------------------------------------------------------------------
__global__ __launch_bounds__(256)
void dyn_conv_mish(const float* __restrict__ x, const float* __restrict__ w,
                   float* __restrict__ out)
{
    const int H = 256, HO = 255;
    __shared__ float ws[32 * 16];
    __shared__ float xs[19][19];

    int b  = blockIdx.z;
    int y0 = blockIdx.y * 16;
    int x0 = blockIdx.x * 16;
    int tid = threadIdx.x;

    for (int i = tid; i < 512; i += 256) ws[i] = w[b * 512 + i];
    for (int i = tid; i < 19 * 19; i += 256) {
        int yy = i / 19, xx = i - yy * 19;
        int gy = y0 - 1 + yy, gx = x0 - 1 + xx;
        xs[yy][xx] = (gy >= 0 && gy < H && gx >= 0 && gx < H)
                     ? x[(size_t)b * H * H + (size_t)gy * H + gx] : 0.f;
    }
    __syncthreads();

    int r  = tid >> 4;
    int cl = tid & 15;
    int oy = y0 + r, ox = x0 + cl;
    if (oy >= HO || ox >= HO) return;

    float xr[16];
#pragma unroll
    for (int i = 0; i < 4; i++)
#pragma unroll
        for (int j = 0; j < 4; j++) xr[i * 4 + j] = xs[r + i][cl + j];

    float* op = out + (size_t)b * 32 * HO * HO + (size_t)oy * HO + ox;
#pragma unroll
    for (int co = 0; co < 32; co++) {
        float a = 0.f;
#pragma unroll
        for (int t = 0; t < 16; t++) a = fmaf(xr[t], ws[co * 16 + t], a);
        op[(size_t)co * HO * HO] = mishf(a);
    }
}

// ---------------------------------------------------------------------------
__global__ void maxpool_kernel(const float* __restrict__ in, float* __restrict__ out,
                               int BC, int Hi, int Wi)
{
    int Ho = Hi >> 1, Wo = Wi >> 1;
    int total = BC * Ho * Wo;
    int n = blockIdx.x * blockDim.x + threadIdx.x;
    if (n >= total) return;
    int xw = n % Wo; int t = n / Wo;
    int y  = t % Ho; int bc = t / Ho;
    const float* p = in + ((size_t)bc * Hi + 2 * y) * Wi + 2 * xw;
    out[n] = fmaxf(fmaxf(p[0], p[1]), fmaxf(p[Wi], p[Wi + 1]));
}

// ---------------------------------------------------------------------------
// Bilinear x2 upsample, align_corners=True, optional per-channel affine (BN),
// writes into channel-offset region of a concat buffer.
// ---------------------------------------------------------------------------
__global__ void up2_kernel(const float* __restrict__ in, float* __restrict__ out,
                           int C, int H, int W, int dstC, int coff,
                           const float* __restrict__ scale,
                           const float* __restrict__ shift)
{
    int Ho = 2 * H, Wo = 2 * W;
    long long total = (long long)4 * C * Ho * Wo;
    long long n = (long long)blockIdx.x * blockDim.x + threadIdx.x;
    if (n >= total) return;
    int ox = (int)(n % Wo); long long t = n / Wo;
    int oy = (int)(t % Ho); t /= Ho;
    int c  = (int)(t % C);  int b = (int)(t / C);

    float ry = (float)((double)(H - 1) / (double)(2 * H - 1));
    float rx = (float)((double)(W - 1) / (double)(2 * W - 1));
    float sy = (float)oy * ry;
    float sx = (float)ox * rx;
    int y0i = (int)sy;
    int x0i = (int)sx;
    float fy = sy - (float)y0i;
    float fx = sx - (float)x0i;
    int y1i = min(y0i + 1, H - 1);
    int x1i = min(x0i + 1, W - 1);

    const float* p = in + ((size_t)b * C + c) * H * W;
    float a0 = p[(size_t)y0i * W + x0i] * (1.f - fy) + p[(size_t)y1i * W + x0i] * fy;
    float a1 = p[(size_t)y0i * W + x1i] * (1.f - fy) + p[(size_t)y1i * W + x1i] * fy;
    float v  = a0 * (1.f - fx) + a1 * fx;
    if (scale) v = v * scale[c] + shift[c];
    out[((size_t)(b * dstC + coff + c) * Ho + oy) * Wo + ox] = v;
}

// ---------------------------------------------------------------------------
__global__ void concat_copy(const float4* __restrict__ src, float* __restrict__ dst,
                            int C, int HW, int dstC, int coff)
{
    int HW4 = HW >> 2;
    int total = 4 * C * HW4;
    int n = blockIdx.x * blockDim.x + threadIdx.x;
    if (n >= total) return;
    int i = n % HW4; int t = n / HW4;
    int c = t % C;   int b = t / C;
    ((float4*)(dst + (size_t)(b * dstC + coff + c) * HW))[i] = src[n];
}

// ---------------------------------------------------------------------------
// BatchNorm batch-stats -> per-channel affine (scale, shift), two-pass.
// ---------------------------------------------------------------------------
__global__ __launch_bounds__(256)
void bn_stats_kernel(const float* __restrict__ h, const float* __restrict__ g,
                     const float* __restrict__ be, float* __restrict__ scale,
                     float* __restrict__ shift)
{
    __shared__ float red[256];
    int c   = blockIdx.x;
    int tid = threadIdx.x;

    float s = 0.f;
    for (int b = 0; b < 4; b++) {
        const float* p = h + ((size_t)b * 512 + c) * 1024;
        for (int i = tid; i < 1024; i += 256) s += p[i];
    }
    red[tid] = s; __syncthreads();
    for (int o = 128; o > 0; o >>= 1) {
        if (tid < o) red[tid] += red[tid + o];
        __syncthreads();
    }
    float mean = red[0] * (1.f / 4096.f);
    __syncthreads();

    float q = 0.f;
    for (int b = 0; b < 4; b++) {
        const float* p = h + ((size_t)b * 512 + c) * 1024;
        for (int i = tid; i < 1024; i += 256) { float d = p[i] - mean; q += d * d; }
    }
    red[tid] = q; __syncthreads();
    for (int o = 128; o > 0; o >>= 1) {
        if (tid < o) red[tid] += red[tid + o];
        __syncthreads();
    }
    if (tid == 0) {
        float var = red[0] * (1.f / 4096.f);
        float sc  = g[c] * rsqrtf(var + 1e-5f);
        scale[c] = sc;
        shift[c] = be[c] - mean * sc;
    }
}

// ---------------------------------------------------------------------------
// Final 1x1 conv, Co=1, no activation.
// ---------------------------------------------------------------------------
__global__ void conv1x1_out(const float* __restrict__ in, const float* __restrict__ wl,
                            const float* __restrict__ bl, float* __restrict__ out)
{
    __shared__ float w[32];
    if (threadIdx.x < 32) w[threadIdx.x] = wl[threadIdx.x];
    __syncthreads();
    int n = blockIdx.x * blockDim.x + threadIdx.x;
    if (n >= 4 * 65536) return;
    int b = n >> 16;
    int i = n & 65535;
    const float* p = in + (size_t)b * 32 * 65536 + i;
    float s = bl[0];
#pragma unroll
    for (int c = 0; c < 32; c++) s = fmaf(p[(size_t)c * 65536], w[c], s);
    out[n] = s;
}

// ---------------------------------------------------------------------------
// Host side
// ---------------------------------------------------------------------------
static void conv3(const float* in, const float* wt, const float* bs, float* out,
                  int Ci, int HW, int Co)
{
    dim3 g((HW / 8) * (HW / 16), Co / 32, 4);
    conv_mish_kernel<3><<<g, 128>>>(in, wt, bs, out, Ci, HW, HW, Co, HW, HW, 1);
}

extern "C" void kernel_launch(void* const* d_in, const int* in_sizes, int n_in,
                              void* d_out, int out_size)
{
    const float* X    = (const float*)d_in[0];
    const float* W    = (const float*)d_in[1];
    const float* d1w  = (const float*)d_in[2];
    const float* d1b  = (const float*)d_in[3];
    const float* w2a  = (const float*)d_in[4];
    const float* b2a  = (const float*)d_in[5];
    const float* w2b  = (const float*)d_in[6];
    const float* b2b  = (const float*)d_in[7];
    const float* w3a  = (const float*)d_in[8];
    const float* b3a  = (const float*)d_in[9];
    const float* w3b  = (const float*)d_in[10];
    const float* b3b  = (const float*)d_in[11];
    const float* w4a  = (const float*)d_in[12];
    const float* b4a  = (const float*)d_in[13];
    const float* w4b  = (const float*)d_in[14];
    const float* b4b  = (const float*)d_in[15];
    const float* g4   = (const float*)d_in[16];
    const float* be4  = (const float*)d_in[17];
    const float* u3a  = (const float*)d_in[18];
    const float* ub3a = (const float*)d_in[19];
    const float* u3b  = (const float*)d_in[20];
    const float* ub3b = (const float*)d_in[21];
    const float* u2a  = (const float*)d_in[22];
    const float* ub2a = (const float*)d_in[23];
    const float* u2b  = (const float*)d_in[24];
    const float* ub2b = (const float*)d_in[25];
    const float* u1a  = (const float*)d_in[26];
    const float* ub1a = (const float*)d_in[27];
    const float* u1b  = (const float*)d_in[28];
    const float* ub1b = (const float*)d_in[29];
    const float* wl   = (const float*)d_in[30];
    const float* bl   = (const float*)d_in[31];

    void *pa, *pb, *pc1, *pc2, *pc3, *pbs, *pbb;
    cudaGetSymbolAddress(&pa,  g_SA);
    cudaGetSymbolAddress(&pb,  g_SB);
    cudaGetSymbolAddress(&pc1, g_C1);
    cudaGetSymbolAddress(&pc2, g_C2);
    cudaGetSymbolAddress(&pc3, g_C3);
    cudaGetSymbolAddress(&pbs, g_BNscale);
    cudaGetSymbolAddress(&pbb, g_BNshift);
    float* SA  = (float*)pa;
    float* SB  = (float*)pb;
    float* C1  = (float*)pc1;
    float* C2  = (float*)pc2;
    float* C3  = (float*)pc3;
    float* BNS = (float*)pbs;
    float* BNB = (float*)pbb;

    // --- Encoder ---
    dyn_conv_mish<<<dim3(16, 16, 4), 256>>>(X, W, SA);

    {   // d1: K=4, pad=2, 255->256 + mish -> C1 (4,32,256,256)
        dim3 g((256 / 8) * (256 / 16), 1, 4);
        conv_mish_kernel<4><<<g, 128>>>(SA, d1w, d1b, C1, 32, 255, 255, 32, 256, 256, 2);
    }

    maxpool_kernel<<<cdiv(4 * 32 * 128 * 128, 256), 256>>>(C1, SB, 4 * 32, 256, 256);

    conv3(SB, w2a, b2a, SA, 32, 128, 128);
    conv3(SA, w2b, b2b, C2, 128, 128, 128);

    maxpool_kernel<<<cdiv(4 * 128 * 64 * 64, 256), 256>>>(C2, SA, 4 * 128, 128, 128);

    conv3(SA, w3a, b3a, SB, 128, 64, 256);
    conv3(SB, w3b, b3b, C3, 256, 64, 256);

    maxpool_kernel<<<cdiv(4 * 256 * 32 * 32, 256), 256>>>(C3, SA, 4 * 256, 64, 64);

    conv3(SA, w4a, b4a, SB, 256, 32, 512);
    conv3(SB, w4b, b4b, SA, 512, 32, 512);

    bn_stats_kernel<<<512, 256>>>(SA, g4, be4, BNS, BNB);

    // --- Decoder ---
    up2_kernel<<<cdiv(4 * 512 * 64 * 64, 256), 256>>>(SA, SB, 512, 32, 32, 768, 0, BNS, BNB);
    concat_copy<<<cdiv(4 * 256 * (64 * 64 / 4), 256), 256>>>((const float4*)C3, SB, 256, 64 * 64, 768, 512);

    conv3(SB, u3a, ub3a, SA, 768, 64, 256);
    conv3(SA, u3b, ub3b, SB, 256, 64, 256);

    up2_kernel<<<cdiv(4 * 256 * 128 * 128, 256), 256>>>(SB, SA, 256, 64, 64, 384, 0, nullptr, nullptr);
    concat_copy<<<cdiv(4 * 128 * (128 * 128 / 4), 256), 256>>>((const float4*)C2, SA, 128, 128 * 128, 384, 256);

    conv3(SA, u2a, ub2a, SB, 384, 128, 128);
    conv3(SB, u2b, ub2b, SA, 128, 128, 128);

    up2_kernel<<<cdiv(4 * 128 * 256 * 256, 256), 256>>>(SA, SB, 128, 128, 128, 160, 0, nullptr, nullptr);
    concat_copy<<<cdiv(4 * 32 * (256 * 256 / 4), 256), 256>>>((const float4*)C1, SB, 32, 256 * 256, 160, 128);

    conv3(SB, u1a, ub1a, SA, 160, 256, 32);
    conv3(SA, u1b, ub1b, SB, 32, 256, 32);

    conv1x1_out<<<cdiv(4 * 65536, 256), 256>>>(SB, wl, bl, (float*)d_out);
}

// round 17
// speedup vs baseline: 1.3663x; 1.0070x over previous
#include <cuda_runtime.h>
#include <math.h>

// ---------------------------------------------------------------------------
// Static device scratch (ping-pong A/B + skips + transposed-weight scratch).
// ---------------------------------------------------------------------------
__device__ float g_SA[25165824];
__device__ float g_SB[41943040];
__device__ float g_C1[8388608];   // (4,32,256,256)
__device__ float g_C2[8388608];   // (4,128,128,128)
__device__ float g_C3[4194304];   // (4,256,64,64)
__device__ float g_WT[1769472];   // max weights: 768*9*256
__device__ float g_BNscale[512];
__device__ float g_BNshift[512];

static inline int cdiv(int a, int b) { return (a + b - 1) / b; }

__device__ __forceinline__ float mishf(float x) {
    float sp = fmaxf(x, 0.f) + log1pf(expf(-fabsf(x)));
    return x * tanhf(sp);
}

__device__ __forceinline__ unsigned smem_u32(const void* p) {
    return (unsigned)__cvta_generic_to_shared(p);
}
__device__ __forceinline__ void cpa16(unsigned d, const void* s) {
    asm volatile("cp.async.ca.shared.global [%0], [%1], 16;" :: "r"(d), "l"(s));
}
__device__ __forceinline__ void cpa4z(unsigned d, const void* s, int sz) {
    asm volatile("cp.async.ca.shared.global [%0], [%1], 4, %2;" :: "r"(d), "l"(s), "r"(sz));
}

// ---------------------------------------------------------------------------
// Weight pre-transpose: wt[co][ci][ij]  ->  wT[(chunk*PER + rem)*Co + co]
// where rem = (ci - chunk*8)*K2 + ij.  Write-coalesced; runs once per layer.
// ---------------------------------------------------------------------------
__global__ void transpose_w(const float* __restrict__ wt, float* __restrict__ wT,
                            int Ci, int Co, int K2)
{
    int PER = 8 * K2;
    int N = Ci * K2 * Co;
    int e = blockIdx.x * 256 + threadIdx.x;
    if (e >= N) return;
    int co = e % Co;
    int t  = e / Co;                 // chunk*PER + rem
    int chunk = t / PER;
    int rem   = t - chunk * PER;
    int lci   = rem / K2;
    int ij    = rem - lci * K2;
    int ci    = chunk * 8 + lci;
    wT[e] = wt[((size_t)co * Ci + ci) * K2 + ij];
}

// ---------------------------------------------------------------------------
// Generic direct conv + bias + mish. cp.async double-buffered, hoisted load
// state. Weights come PRE-TRANSPOSED (see transpose_w): smem [rem][co32] so
// the 4 co-weights per thread are one broadcast LDS.128. Input rows padded to
// even stride so taps load as aligned LDS.64.
// Block: 128 threads -> 32 co x (8x16 px), 1 batch.
// Requires: Ci % 8 == 0, Co % 32 == 0, Ho % 8 == 0, Wo % 16 == 0.
// ---------------------------------------------------------------------------
template<int K>
__global__ __launch_bounds__(128, 5)
void conv_mish_kernel(const float* __restrict__ in, const float* __restrict__ wt,
                      const float* __restrict__ bias, float* __restrict__ out,
                      int Ci, int Hi, int Wi, int Co, int Ho, int Wo, int pad)
{
    constexpr int K2    = K * K;
    constexpr int CI_CH = 8;
    constexpr int CO_T  = 32;
    constexpr int TH    = 8;
    constexpr int TW    = 16;
    constexpr int XH    = TH + K - 1;
    constexpr int XW    = TW + K - 1;          // 18 / 19
    constexpr int XWP   = (XW + 1) & ~1;       // 18 / 20 (even stride)
    constexpr int TILE  = XH * XWP;            // 180 / 220
    constexpr int PER   = CI_CH * K2;          // weight rems per chunk
    constexpr int WSZ   = CO_T * PER;          // weight floats per chunk
    constexpr int WSZ4  = WSZ / 4;             // 16B units
    constexpr int XS    = CI_CH * TILE;
    constexpr int NW    = (WSZ4 + 127) / 128;
    constexpr int NX    = (TILE + 127) / 128;
    constexpr int NF2   = (8 + K) / 2;         // float2 loads per row (5 / 6)

    __shared__ __align__(16) float ws[2][WSZ];
    __shared__ __align__(16) float xs[2][XS];

    const int b   = blockIdx.z;
    const int co0 = blockIdx.y * CO_T;
    const int ntx = Wo / TW;
    const int ty  = blockIdx.x / ntx;
    const int tx  = blockIdx.x - ty * ntx;
    const int y0  = ty * TH;
    const int x0  = tx * TW;

    const int tid = threadIdx.x;
    const int cog = tid >> 4;              // 0..7 -> co_local = cog*4
    const int pg  = tid & 15;
    const int r   = pg >> 1;               // row within tile (0..7)
    const int c0  = (pg & 1) * 8;          // col base (0 or 8), even

    const float* inb  = in + (size_t)b * Ci * Hi * Wi;
    const size_t HiWi = (size_t)Hi * Wi;

    // ---- hoisted per-thread load state ----
    // weights: transposed layout; slot v covers (rem = v/8, co4 = v%8)
    const float* wptr[NW];
#pragma unroll
    for (int s = 0; s < NW; s++) {
        int v = tid + s * 128;
        if (v < WSZ4) {
            int rem = v >> 3;
            int co4 = v & 7;
            wptr[s] = wt + (size_t)rem * Co + co0 + co4 * 4;
        }
    }
    const size_t wstep = (size_t)PER * Co;

    const float* xptr[NX];
    int xsz[NX];
#pragma unroll
    for (int s = 0; s < NX; s++) {
        int pos = tid + s * 128;
        int yy  = pos / XWP;
        int xx  = pos - yy * XWP;
        int gy  = y0 - pad + yy;
        int gx  = x0 - pad + xx;
        bool ok = (pos < TILE) && (xx < XW) && gy >= 0 && gy < Hi && gx >= 0 && gx < Wi;
        xptr[s] = ok ? (inb + (size_t)gy * Wi + gx) : inb;
        xsz[s]  = ok ? 4 : 0;
    }
    const unsigned wsb = smem_u32(&ws[0][0]);
    const unsigned xsb = smem_u32(&xs[0][0]);

    float acc[4][8];
#pragma unroll
    for (int a = 0; a < 4; a++)
#pragma unroll
        for (int p = 0; p < 8; p++) acc[a][p] = 0.f;

    // ---- async issue of one ci-chunk into buffer `buf` ----
    auto issue = [&](int buf) {
#pragma unroll
        for (int s = 0; s < NW; s++) {
            int v = tid + s * 128;
            if (v < WSZ4) {
                cpa16(wsb + buf * (WSZ * 4) + v * 16, wptr[s]);
                wptr[s] += wstep;
            }
        }
#pragma unroll
        for (int s = 0; s < NX; s++) {
            if (s < TILE / 128 || tid < (TILE & 127)) {
                unsigned d = xsb + buf * (XS * 4) + (tid + s * 128) * 4;
                const float* p = xptr[s];
#pragma unroll
                for (int ci = 0; ci < CI_CH; ci++) {
                    cpa4z(d + ci * (TILE * 4), p, xsz[s]);
                    p += HiWi;
                }
                xptr[s] = p;
            }
        }
    };

    const int nchunks = Ci / CI_CH;
    issue(0);
    asm volatile("cp.async.commit_group;");

    for (int c = 0; c < nchunks; c++) {
        const int buf = c & 1;
        if (c + 1 < nchunks) {
            issue(buf ^ 1);
            asm volatile("cp.async.commit_group;");
            asm volatile("cp.async.wait_group 1;");
        } else {
            asm volatile("cp.async.wait_group 0;");
        }
        __syncthreads();

        const float4* ws4 = (const float4*)ws[buf];
        const float*  xsc = xs[buf];
#pragma unroll
        for (int ci = 0; ci < CI_CH; ci++) {
            const float* xb = &xsc[ci * TILE];
#pragma unroll
            for (int i = 0; i < K; i++) {
                const float2* xp2 = (const float2*)(xb + (r + i) * XWP + c0);
                float2 A[NF2];
#pragma unroll
                for (int t = 0; t < NF2; t++) A[t] = xp2[t];
                float xr[2 * NF2];
#pragma unroll
                for (int t = 0; t < NF2; t++) { xr[2*t] = A[t].x; xr[2*t+1] = A[t].y; }
#pragma unroll
                for (int j = 0; j < K; j++) {
                    float4 w = ws4[(ci * K2 + i * K + j) * (CO_T / 4) + cog];
#pragma unroll
                    for (int p = 0; p < 8; p++) {
                        float xv = xr[j + p];
                        acc[0][p] = fmaf(w.x, xv, acc[0][p]);
                        acc[1][p] = fmaf(w.y, xv, acc[1][p]);
                        acc[2][p] = fmaf(w.z, xv, acc[2][p]);
                        acc[3][p] = fmaf(w.w, xv, acc[3][p]);
                    }
                }
            }
        }
        __syncthreads();
    }

#pragma unroll
    for (int a = 0; a < 4; a++) {
        int co   = co0 + cog * 4 + a;
        float bv = bias[co];
        float* op = out + ((size_t)b * Co + co) * Ho * Wo
                        + (size_t)(y0 + r) * Wo + x0 + c0;
#pragma unroll
        for (int p = 0; p < 8; p++)
            op[p] = mishf(acc[a][p] + bv);
    }
}

// ---------------------------------------------------------------------------
// Per-sample dynamic conv (Ci=1, K=4, pad=1) + mish. x:(4,1,256,256),
// w:(4,32,4,4) -> out:(4,32,255,255).
// ---------------------------------------------------------------------------
__global__ __launch_bounds__(256)
void dyn_conv_mish(const float* __restrict__ x, const float* __restrict__ w,
                   float* __restrict__ out)
{
    const int H = 256, HO = 255;
    __shared__ float ws[32 * 16];
    __shared__ float xs[19][19];

    int b  = blockIdx.z;
    int y0 = blockIdx.y * 16;
    int x0 = blockIdx.x * 16;
    int tid = threadIdx.x;

    for (int i = tid; i < 512; i += 256) ws[i] = w[b * 512 + i];
    for (int i = tid; i < 19 * 19; i += 256) {
        int yy = i / 19, xx = i - yy * 19;
        int gy = y0 - 1 + yy, gx = x0 - 1 + xx;
        xs[yy][xx] = (gy >= 0 && gy < H && gx >= 0 && gx < H)
                     ? x[(size_t)b * H * H + (size_t)gy * H + gx] : 0.f;
    }
    __syncthreads();

    int r  = tid >> 4;
    int cl = tid & 15;
    int oy = y0 + r, ox = x0 + cl;
    if (oy >= HO || ox >= HO) return;

    float xr[16];
#pragma unroll
    for (int i = 0; i < 4; i++)
#pragma unroll
        for (int j = 0; j < 4; j++) xr[i * 4 + j] = xs[r + i][cl + j];

    float* op = out + (size_t)b * 32 * HO * HO + (size_t)oy * HO + ox;
#pragma unroll
    for (int co = 0; co < 32; co++) {
        float a = 0.f;
#pragma unroll
        for (int t = 0; t < 16; t++) a = fmaf(xr[t], ws[co * 16 + t], a);
        op[(size_t)co * HO * HO] = mishf(a);
    }
}

// ---------------------------------------------------------------------------
__global__ void maxpool_kernel(const float* __restrict__ in, float* __restrict__ out,
                               int BC, int Hi, int Wi)
{
    int Ho = Hi >> 1, Wo = Wi >> 1;
    int total = BC * Ho * Wo;
    int n = blockIdx.x * blockDim.x + threadIdx.x;
    if (n >= total) return;
    int xw = n % Wo; int t = n / Wo;
    int y  = t % Ho; int bc = t / Ho;
    const float* p = in + ((size_t)bc * Hi + 2 * y) * Wi + 2 * xw;
    out[n] = fmaxf(fmaxf(p[0], p[1]), fmaxf(p[Wi], p[Wi + 1]));
}

// ---------------------------------------------------------------------------
// Bilinear x2 upsample, align_corners=True, optional per-channel affine (BN),
// writes into channel-offset region of a concat buffer.
// ---------------------------------------------------------------------------
__global__ void up2_kernel(const float* __restrict__ in, float* __restrict__ out,
                           int C, int H, int W, int dstC, int coff,
                           const float* __restrict__ scale,
                           const float* __restrict__ shift)
{
    int Ho = 2 * H, Wo = 2 * W;
    long long total = (long long)4 * C * Ho * Wo;
    long long n = (long long)blockIdx.x * blockDim.x + threadIdx.x;
    if (n >= total) return;
    int ox = (int)(n % Wo); long long t = n / Wo;
    int oy = (int)(t % Ho); t /= Ho;
    int c  = (int)(t % C);  int b = (int)(t / C);

    float ry = (float)((double)(H - 1) / (double)(2 * H - 1));
    float rx = (float)((double)(W - 1) / (double)(2 * W - 1));
    float sy = (float)oy * ry;
    float sx = (float)ox * rx;
    int y0i = (int)sy;
    int x0i = (int)sx;
    float fy = sy - (float)y0i;
    float fx = sx - (float)x0i;
    int y1i = min(y0i + 1, H - 1);
    int x1i = min(x0i + 1, W - 1);

    const float* p = in + ((size_t)b * C + c) * H * W;
    float a0 = p[(size_t)y0i * W + x0i] * (1.f - fy) + p[(size_t)y1i * W + x0i] * fy;
    float a1 = p[(size_t)y0i * W + x1i] * (1.f - fy) + p[(size_t)y1i * W + x1i] * fy;
    float v  = a0 * (1.f - fx) + a1 * fx;
    if (scale) v = v * scale[c] + shift[c];
    out[((size_t)(b * dstC + coff + c) * Ho + oy) * Wo + ox] = v;
}

// ---------------------------------------------------------------------------
__global__ void concat_copy(const float4* __restrict__ src, float* __restrict__ dst,
                            int C, int HW, int dstC, int coff)
{
    int HW4 = HW >> 2;
    int total = 4 * C * HW4;
    int n = blockIdx.x * blockDim.x + threadIdx.x;
    if (n >= total) return;
    int i = n % HW4; int t = n / HW4;
    int c = t % C;   int b = t / C;
    ((float4*)(dst + (size_t)(b * dstC + coff + c) * HW))[i] = src[n];
}

// ---------------------------------------------------------------------------
// BatchNorm batch-stats -> per-channel affine (scale, shift), two-pass.
// ---------------------------------------------------------------------------
__global__ __launch_bounds__(256)
void bn_stats_kernel(const float* __restrict__ h, const float* __restrict__ g,
                     const float* __restrict__ be, float* __restrict__ scale,
                     float* __restrict__ shift)
{
    __shared__ float red[256];
    int c   = blockIdx.x;
    int tid = threadIdx.x;

    float s = 0.f;
    for (int b = 0; b < 4; b++) {
        const float* p = h + ((size_t)b * 512 + c) * 1024;
        for (int i = tid; i < 1024; i += 256) s += p[i];
    }
    red[tid] = s; __syncthreads();
    for (int o = 128; o > 0; o >>= 1) {
        if (tid < o) red[tid] += red[tid + o];
        __syncthreads();
    }
    float mean = red[0] * (1.f / 4096.f);
    __syncthreads();

    float q = 0.f;
    for (int b = 0; b < 4; b++) {
        const float* p = h + ((size_t)b * 512 + c) * 1024;
        for (int i = tid; i < 1024; i += 256) { float d = p[i] - mean; q += d * d; }
    }
    red[tid] = q; __syncthreads();
    for (int o = 128; o > 0; o >>= 1) {
        if (tid < o) red[tid] += red[tid + o];
        __syncthreads();
    }
    if (tid == 0) {
        float var = red[0] * (1.f / 4096.f);
        float sc  = g[c] * rsqrtf(var + 1e-5f);
        scale[c] = sc;
        shift[c] = be[c] - mean * sc;
    }
}

// ---------------------------------------------------------------------------
// Final 1x1 conv, Co=1, no activation.
// ---------------------------------------------------------------------------
__global__ void conv1x1_out(const float* __restrict__ in, const float* __restrict__ wl,
                            const float* __restrict__ bl, float* __restrict__ out)
{
    __shared__ float w[32];
    if (threadIdx.x < 32) w[threadIdx.x] = wl[threadIdx.x];
    __syncthreads();
    int n = blockIdx.x * blockDim.x + threadIdx.x;
    if (n >= 4 * 65536) return;
    int b = n >> 16;
    int i = n & 65535;
    const float* p = in + (size_t)b * 32 * 65536 + i;
    float s = bl[0];
#pragma unroll
    for (int c = 0; c < 32; c++) s = fmaf(p[(size_t)c * 65536], w[c], s);
    out[n] = s;
}

// ---------------------------------------------------------------------------
// Host side
// ---------------------------------------------------------------------------
static float* g_WT_ptr;

static void conv3(const float* in, const float* wt, const float* bs, float* out,
                  int Ci, int HW, int Co)
{
    int N = Ci * 9 * Co;
    transpose_w<<<cdiv(N, 256), 256>>>(wt, g_WT_ptr, Ci, Co, 9);
    dim3 g((HW / 8) * (HW / 16), Co / 32, 4);
    conv_mish_kernel<3><<<g, 128>>>(in, g_WT_ptr, bs, out, Ci, HW, HW, Co, HW, HW, 1);
}

extern "C" void kernel_launch(void* const* d_in, const int* in_sizes, int n_in,
                              void* d_out, int out_size)
{
    const float* X    = (const float*)d_in[0];
    const float* W    = (const float*)d_in[1];
    const float* d1w  = (const float*)d_in[2];
    const float* d1b  = (const float*)d_in[3];
    const float* w2a  = (const float*)d_in[4];
    const float* b2a  = (const float*)d_in[5];
    const float* w2b  = (const float*)d_in[6];
    const float* b2b  = (const float*)d_in[7];
    const float* w3a  = (const float*)d_in[8];
    const float* b3a  = (const float*)d_in[9];
    const float* w3b  = (const float*)d_in[10];
    const float* b3b  = (const float*)d_in[11];
    const float* w4a  = (const float*)d_in[12];
    const float* b4a  = (const float*)d_in[13];
    const float* w4b  = (const float*)d_in[14];
    const float* b4b  = (const float*)d_in[15];
    const float* g4   = (const float*)d_in[16];
    const float* be4  = (const float*)d_in[17];
    const float* u3a  = (const float*)d_in[18];
    const float* ub3a = (const float*)d_in[19];
    const float* u3b  = (const float*)d_in[20];
    const float* ub3b = (const float*)d_in[21];
    const float* u2a  = (const float*)d_in[22];
    const float* ub2a = (const float*)d_in[23];
    const float* u2b  = (const float*)d_in[24];
    const float* ub2b = (const float*)d_in[25];
    const float* u1a  = (const float*)d_in[26];
    const float* ub1a = (const float*)d_in[27];
    const float* u1b  = (const float*)d_in[28];
    const float* ub1b = (const float*)d_in[29];
    const float* wl   = (const float*)d_in[30];
    const float* bl   = (const float*)d_in[31];

    void *pa, *pb, *pc1, *pc2, *pc3, *pwt, *pbs, *pbb;
    cudaGetSymbolAddress(&pa,  g_SA);
    cudaGetSymbolAddress(&pb,  g_SB);
    cudaGetSymbolAddress(&pc1, g_C1);
    cudaGetSymbolAddress(&pc2, g_C2);
    cudaGetSymbolAddress(&pc3, g_C3);
    cudaGetSymbolAddress(&pwt, g_WT);
    cudaGetSymbolAddress(&pbs, g_BNscale);
    cudaGetSymbolAddress(&pbb, g_BNshift);
    float* SA  = (float*)pa;
    float* SB  = (float*)pb;
    float* C1  = (float*)pc1;
    float* C2  = (float*)pc2;
    float* C3  = (float*)pc3;
    g_WT_ptr   = (float*)pwt;
    float* BNS = (float*)pbs;
    float* BNB = (float*)pbb;

    // --- Encoder ---
    dyn_conv_mish<<<dim3(16, 16, 4), 256>>>(X, W, SA);

    {   // d1: K=4, pad=2, 255->256 + mish -> C1 (4,32,256,256)
        int N = 32 * 16 * 32;
        transpose_w<<<cdiv(N, 256), 256>>>(d1w, g_WT_ptr, 32, 32, 16);
        dim3 g((256 / 8) * (256 / 16), 1, 4);
        conv_mish_kernel<4><<<g, 128>>>(SA, g_WT_ptr, d1b, C1, 32, 255, 255, 32, 256, 256, 2);
    }

    maxpool_kernel<<<cdiv(4 * 32 * 128 * 128, 256), 256>>>(C1, SB, 4 * 32, 256, 256);

    conv3(SB, w2a, b2a, SA, 32, 128, 128);
    conv3(SA, w2b, b2b, C2, 128, 128, 128);

    maxpool_kernel<<<cdiv(4 * 128 * 64 * 64, 256), 256>>>(C2, SA, 4 * 128, 128, 128);

    conv3(SA, w3a, b3a, SB, 128, 64, 256);
    conv3(SB, w3b, b3b, C3, 256, 64, 256);

    maxpool_kernel<<<cdiv(4 * 256 * 32 * 32, 256), 256>>>(C3, SA, 4 * 256, 64, 64);

    conv3(SA, w4a, b4a, SB, 256, 32, 512);
    conv3(SB, w4b, b4b, SA, 512, 32, 512);

    bn_stats_kernel<<<512, 256>>>(SA, g4, be4, BNS, BNB);

    // --- Decoder ---
    up2_kernel<<<cdiv(4 * 512 * 64 * 64, 256), 256>>>(SA, SB, 512, 32, 32, 768, 0, BNS, BNB);
    concat_copy<<<cdiv(4 * 256 * (64 * 64 / 4), 256), 256>>>((const float4*)C3, SB, 256, 64 * 64, 768, 512);

    conv3(SB, u3a, ub3a, SA, 768, 64, 256);
    conv3(SA, u3b, ub3b, SB, 256, 64, 256);

    up2_kernel<<<cdiv(4 * 256 * 128 * 128, 256), 256>>>(SB, SA, 256, 64, 64, 384, 0, nullptr, nullptr);
    concat_copy<<<cdiv(4 * 128 * (128 * 128 / 4), 256), 256>>>((const float4*)C2, SA, 128, 128 * 128, 384, 256);

    conv3(SA, u2a, ub2a, SB, 384, 128, 128);
    conv3(SB, u2b, ub2b, SA, 128, 128, 128);

    up2_kernel<<<cdiv(4 * 128 * 256 * 256, 256), 256>>>(SA, SB, 128, 128, 128, 160, 0, nullptr, nullptr);
    concat_copy<<<cdiv(4 * 32 * (256 * 256 / 4), 256), 256>>>((const float4*)C1, SB, 32, 256 * 256, 160, 128);

    conv3(SB, u1a, ub1a, SA, 160, 256, 32);
    conv3(SA, u1b, ub1b, SB, 32, 256, 32);

    conv1x1_out<<<cdiv(4 * 65536, 256), 256>>>(SB, wl, bl, (float*)d_out);
}